// round 1
// baseline (speedup 1.0000x reference)
#include <cuda_runtime.h>
#include <cuda_bf16.h>
#include <math.h>
#include <stdint.h>

// ---------------- problem constants ----------------
#define Bq   2
#define Lq   4096
#define DIMq 512
#define Hq   4
#define DHq  128
#define Cq   64
#define Nq   64          // L / C
#define BHq  8           // B * H
#define NCHUNK 512       // BH * N
#define MAXLR 0.01f
#define EPSq  1e-6f

// ---------------- scratch (device globals; allocation-free) ----------------
__device__ float d_s_norm[Bq*Lq*DIMq];
__device__ float d_r_norm[Bq*Lq*DIMq];
__device__ float d_qin   [Bq*Lq*DIMq];
__device__ float d_keys  [BHq*Lq*DHq];
__device__ float d_vals  [BHq*Lq*DHq];
__device__ float d_quer  [BHq*Lq*DHq];
__device__ float d_lr    [BHq*Lq];
__device__ float d_seqmean[Bq*Nq*DIMq];
__device__ float d_am    [BHq*Nq];
__device__ float d_dc    [BHq*Nq];
__device__ float d_g0    [NCHUNK*DHq*DHq];
__device__ float d_g1    [NCHUNK*DHq*DHq];
__device__ float d_w0t   [NCHUNK*DHq*DHq];
__device__ float d_w1t   [NCHUNK*DHq*DHq];
__device__ float d_comb  [Bq*Lq*DIMq];
__device__ float d_gatev [Bq*Lq*Hq];

__device__ __forceinline__ float sigm(float x){ return 1.f/(1.f+expf(-x)); }

// ---------------- K1: per-token rmsnorm (both scales) ----------------
__global__ void __launch_bounds__(128) norm_kernel(const float* __restrict__ seq,
                                                   const float* __restrict__ ss,
                                                   const float* __restrict__ rs)
{
    int token = blockIdx.x;              // b*L + t
    int tid = threadIdx.x;
    const float* x = seq + (size_t)token*DIMq;
    float v[4]; float acc = 0.f;
#pragma unroll
    for (int i=0;i<4;i++){ v[i] = x[tid + 128*i]; acc += v[i]*v[i]; }
#pragma unroll
    for (int off=16;off;off>>=1) acc += __shfl_down_sync(0xffffffffu, acc, off);
    __shared__ float red[4];
    if ((tid&31)==0) red[tid>>5] = acc;
    __syncthreads();
    float tot = red[0]+red[1]+red[2]+red[3];
    float rms = rsqrtf(tot*(1.f/DIMq) + EPSq);
#pragma unroll
    for (int i=0;i<4;i++){
        int d = tid + 128*i;
        float y = v[i]*rms;
        d_s_norm[(size_t)token*DIMq + d] = y*ss[d];
        d_r_norm[(size_t)token*DIMq + d] = y*rs[d];
    }
}

// ---------------- K2: shifted copy  q_in[b,t] = r[b,t+C-1] or 0 ----------------
__global__ void shift_kernel()
{
    size_t gid = (size_t)blockIdx.x*blockDim.x + threadIdx.x;
    if (gid >= (size_t)Bq*Lq*DIMq) return;
    int d = gid & (DIMq-1);
    size_t row = gid / DIMq;
    int t = (int)(row & (Lq-1));
    int b = (int)(row >> 12);
    float val = 0.f;
    if (t + Cq - 1 < Lq)
        val = d_r_norm[((size_t)b*Lq + t + Cq - 1)*DIMq + d];
    d_qin[gid] = val;
}

// ---------------- K3: chunk means of s ----------------
__global__ void __launch_bounds__(512) chunk_mean_kernel()
{
    int bn = blockIdx.x;            // b*N + n
    int d = threadIdx.x;
    int b = bn / Nq, n = bn % Nq;
    const float* base = d_s_norm + ((size_t)b*Lq + n*Cq)*DIMq + d;
    float acc = 0.f;
#pragma unroll 8
    for (int c=0;c<Cq;c++) acc += base[(size_t)c*DIMq];
    d_seqmean[(size_t)bn*DIMq + d] = acc*(1.f/Cq);
}

// ---------------- K4: tiny 512->4 projections (lr / gate) ----------------
template<int MODE>   // 0: lr (sigmoid*MAXLR, head-major layout), 1: gate (sigmoid, token-major)
__global__ void proj4_kernel(const float* __restrict__ X, const float* __restrict__ W, float* __restrict__ out)
{
    int warp = (blockIdx.x*blockDim.x + threadIdx.x) >> 5;
    int lane = threadIdx.x & 31;
    if (warp >= Bq*Lq) return;
    const float* x = X + (size_t)warp*DIMq;
    float a0=0.f,a1=0.f,a2=0.f,a3=0.f;
    for (int d=lane; d<DIMq; d+=32){
        float xv = x[d];
        a0 += xv*W[d*4+0]; a1 += xv*W[d*4+1]; a2 += xv*W[d*4+2]; a3 += xv*W[d*4+3];
    }
#pragma unroll
    for (int off=16;off;off>>=1){
        a0 += __shfl_down_sync(0xffffffffu,a0,off);
        a1 += __shfl_down_sync(0xffffffffu,a1,off);
        a2 += __shfl_down_sync(0xffffffffu,a2,off);
        a3 += __shfl_down_sync(0xffffffffu,a3,off);
    }
    if (lane==0){
        int b = warp >> 12, t = warp & (Lq-1);
        if (MODE==0){
            out[((size_t)(b*Hq+0))*Lq + t] = sigm(a0)*MAXLR;
            out[((size_t)(b*Hq+1))*Lq + t] = sigm(a1)*MAXLR;
            out[((size_t)(b*Hq+2))*Lq + t] = sigm(a2)*MAXLR;
            out[((size_t)(b*Hq+3))*Lq + t] = sigm(a3)*MAXLR;
        } else {
            out[(size_t)warp*Hq+0] = sigm(a0);
            out[(size_t)warp*Hq+1] = sigm(a1);
            out[(size_t)warp*Hq+2] = sigm(a2);
            out[(size_t)warp*Hq+3] = sigm(a3);
        }
    }
}

// ---------------- K5: ada_mom / decay from seq_mean ----------------
__global__ void momdec_kernel(const float* __restrict__ wm, const float* __restrict__ wd)
{
    int warp = (blockIdx.x*blockDim.x + threadIdx.x) >> 5;
    int lane = threadIdx.x & 31;
    if (warp >= Bq*Nq) return;
    const float* x = d_seqmean + (size_t)warp*DIMq;
    float a[4]={0,0,0,0}, b4[4]={0,0,0,0};
    for (int d=lane; d<DIMq; d+=32){
        float xv = x[d];
#pragma unroll
        for (int h=0;h<4;h++){ a[h]+=xv*wm[d*4+h]; b4[h]+=xv*wd[d*4+h]; }
    }
#pragma unroll
    for (int off=16;off;off>>=1)
#pragma unroll
        for (int h=0;h<4;h++){
            a[h]  += __shfl_down_sync(0xffffffffu,a[h],off);
            b4[h] += __shfl_down_sync(0xffffffffu,b4[h],off);
        }
    if (lane==0){
        int b = warp / Nq, n = warp % Nq;
#pragma unroll
        for (int h=0;h<4;h++){
            d_am[(size_t)(b*Hq+h)*Nq + n] = sigm(a[h]);
            d_dc[(size_t)(b*Hq+h)*Nq + n] = sigm(b4[h]);
        }
    }
}

// ---------------- generic SGEMM 128x64 tile, fp32 ----------------
// MODE 0: C -> keys/vals head-major   (Nc=1024)
// MODE 1: C -> queries head-major     (Nc=512)
// MODE 2: C -> final out, shifted +63 (Nc=512)
template<int MODE>
__global__ void __launch_bounds__(256) sgemm_kernel(const float* __restrict__ A,
                                                    const float* __restrict__ W,
                                                    float* __restrict__ out0,
                                                    float* __restrict__ out1,
                                                    int Nc, int K)
{
    __shared__ __align__(16) float As[128*17];
    __shared__ __align__(16) float Bs[16*68];
    int tid = threadIdx.x;
    int tx = tid & 15, ty = tid >> 4;
    int m0 = blockIdx.y*128, n0 = blockIdx.x*64;
    float acc[8][4];
#pragma unroll
    for (int i=0;i<8;i++)
#pragma unroll
        for (int j=0;j<4;j++) acc[i][j]=0.f;

    for (int k0=0;k0<K;k0+=16){
        for (int idx=tid; idx<2048; idx+=256){
            int r = idx>>4, c = idx&15;
            As[r*17+c] = A[(size_t)(m0+r)*K + k0 + c];
        }
        for (int idx=tid; idx<1024; idx+=256){
            int r = idx>>6, c = idx&63;
            Bs[r*68+c] = W[(size_t)(k0+r)*Nc + n0 + c];
        }
        __syncthreads();
#pragma unroll
        for (int kk=0;kk<16;kk++){
            float4 bv = *(const float4*)&Bs[kk*68 + tx*4];
#pragma unroll
            for (int i=0;i<8;i++){
                float av = As[(ty + 16*i)*17 + kk];
                acc[i][0]+=av*bv.x; acc[i][1]+=av*bv.y;
                acc[i][2]+=av*bv.z; acc[i][3]+=av*bv.w;
            }
        }
        __syncthreads();
    }
#pragma unroll
    for (int i=0;i<8;i++){
        int row = m0 + ty + 16*i;
        int b = row >> 12, t = row & (Lq-1);
#pragma unroll
        for (int j=0;j<4;j++){
            int col = n0 + tx*4 + j;
            float v = acc[i][j];
            if (MODE==0){
                if (col < Hq*DHq){
                    int h = col>>7, d = col&127;
                    out0[((size_t)(b*Hq+h)*Lq + t)*DHq + d] = v;
                } else {
                    int c2 = col - Hq*DHq; int h = c2>>7, d = c2&127;
                    out1[((size_t)(b*Hq+h)*Lq + t)*DHq + d] = v;
                }
            } else if (MODE==1){
                int h = col>>7, d = col&127;
                out0[((size_t)(b*Hq+h)*Lq + t)*DHq + d] = v;
            } else {
                if (t <= Lq - Cq)   // only first L-C+1 rows used, shifted by C-1
                    out0[((size_t)b*Lq + t + Cq - 1)*DIMq + col] = v;
            }
        }
    }
}

// ---------------- smem matmul helpers (pitch 129) ----------------
#define PC 129
// O(64x128) = A(64x128) @ W(128x128)
__device__ __forceinline__ void mm64(const float* A, const float* Ws, float* O, int tid)
{
    int tx = tid & 31, ty = tid >> 5;
    float acc[8][4];
#pragma unroll
    for (int r=0;r<8;r++)
#pragma unroll
        for (int c=0;c<4;c++) acc[r][c]=0.f;
#pragma unroll 8
    for (int kk=0;kk<128;kk++){
        float wv[4];
#pragma unroll
        for (int c=0;c<4;c++) wv[c] = Ws[kk*PC + tx + 32*c];
#pragma unroll
        for (int r=0;r<8;r++){
            float av = A[(ty + 8*r)*PC + kk];
#pragma unroll
            for (int c=0;c<4;c++) acc[r][c] += av*wv[c];
        }
    }
#pragma unroll
    for (int r=0;r<8;r++)
#pragma unroll
        for (int c=0;c<4;c++) O[(ty+8*r)*PC + tx + 32*c] = acc[r][c];
}
// G(128x128, gmem row-major) = A^T(128x64) @ Bm(64x128)
__device__ __forceinline__ void mmT(const float* A, const float* Bm, float* __restrict__ G, int tid)
{
    int tx = tid & 31, ty = tid >> 5;
    float acc[16][4];
#pragma unroll
    for (int r=0;r<16;r++)
#pragma unroll
        for (int c=0;c<4;c++) acc[r][c]=0.f;
#pragma unroll 4
    for (int t=0;t<64;t++){
        float bv[4];
#pragma unroll
        for (int c=0;c<4;c++) bv[c] = Bm[t*PC + tx + 32*c];
#pragma unroll
        for (int r=0;r<16;r++){
            float av = A[t*PC + ty + 8*r];
#pragma unroll
            for (int c=0;c<4;c++) acc[r][c] += av*bv[c];
        }
    }
#pragma unroll
    for (int r=0;r<16;r++)
#pragma unroll
        for (int c=0;c<4;c++)
            G[(ty+8*r)*DHq + tx + 32*c] = acc[r][c];
}

// ---------------- K6: per-chunk gradient ----------------
__global__ void __launch_bounds__(256) chunk_grad_kernel(const float* __restrict__ w0,
                                                         const float* __restrict__ w1)
{
    extern __shared__ float sm[];
    float* Ks = sm;               // 64*129
    float* Hb = Ks + 64*PC;
    float* Ab = Hb + 64*PC;
    float* Db = Ab + 64*PC;       // v, then dpred
    float* Ws = Db + 64*PC;       // 128*129
    float* Lr = Ws + 128*PC;      // 64
    int tid = threadIdx.x;
    int chunk = blockIdx.x;
    int bh = chunk >> 6, t0 = (chunk & 63) << 6;

    const float* kg = d_keys + ((size_t)bh*Lq + t0)*DHq;
    const float* vg = d_vals + ((size_t)bh*Lq + t0)*DHq;
    for (int idx=tid; idx<64*128; idx+=256){
        int r = idx>>7, d = idx&127;
        Ks[r*PC+d] = kg[idx];
        Db[r*PC+d] = vg[idx];
    }
    if (tid < 64) Lr[tid] = d_lr[(size_t)bh*Lq + t0 + tid];
    for (int idx=tid; idx<128*128; idx+=256){
        int r = idx>>7, d = idx&127;
        Ws[r*PC+d] = w0[idx];
    }
    __syncthreads();

    mm64(Ks, Ws, Hb, tid);                 // h = k @ w0
    __syncthreads();
    for (int idx=tid; idx<64*128; idx+=256){
        int r = idx>>7, d = idx&127;
        float h = Hb[r*PC+d];
        Ab[r*PC+d] = h / (1.f + expf(-h)); // a = silu(h)
    }
    __syncthreads();
    for (int idx=tid; idx<128*128; idx+=256){
        int r = idx>>7, d = idx&127;
        Ws[r*PC+d] = w1[idx];
    }
    __syncthreads();

    {   // pred = a @ w1 ; dpred = 2*lr/DH * (pred - v)  (into Db)
        int tx = tid & 31, ty = tid >> 5;
        float acc[8][4];
#pragma unroll
        for (int r=0;r<8;r++)
#pragma unroll
            for (int c=0;c<4;c++) acc[r][c]=0.f;
#pragma unroll 8
        for (int kk=0;kk<128;kk++){
            float wv[4];
#pragma unroll
            for (int c=0;c<4;c++) wv[c] = Ws[kk*PC + tx + 32*c];
#pragma unroll
            for (int r=0;r<8;r++){
                float av = Ab[(ty+8*r)*PC + kk];
#pragma unroll
                for (int c=0;c<4;c++) acc[r][c] += av*wv[c];
            }
        }
#pragma unroll
        for (int r=0;r<8;r++){
            int row = ty + 8*r;
            float coef = Lr[row] * (2.f/DHq);
#pragma unroll
            for (int c=0;c<4;c++){
                int col = tx + 32*c;
                float v = Db[row*PC + col];
                Db[row*PC + col] = coef * (acc[r][c] - v);
            }
        }
    }
    __syncthreads();

    mmT(Ab, Db, d_g1 + (size_t)chunk*DHq*DHq, tid);   // g1 = a^T @ dpred
    __syncthreads();

    {   // da = dpred @ w1^T ; dh = da * dsilu(h)  (into Ab)
        int tx = tid & 31, ty = tid >> 5;
        float acc[8][4];
#pragma unroll
        for (int r=0;r<8;r++)
#pragma unroll
            for (int c=0;c<4;c++) acc[r][c]=0.f;
#pragma unroll 8
        for (int j=0;j<128;j++){
            float wv[4];
#pragma unroll
            for (int c=0;c<4;c++) wv[c] = Ws[(tx+32*c)*PC + j];
#pragma unroll
            for (int r=0;r<8;r++){
                float dv = Db[(ty+8*r)*PC + j];
#pragma unroll
                for (int c=0;c<4;c++) acc[r][c] += dv*wv[c];
            }
        }
#pragma unroll
        for (int r=0;r<8;r++)
#pragma unroll
            for (int c=0;c<4;c++){
                int row = ty+8*r, col = tx+32*c;
                float h = Hb[row*PC + col];
                float s = 1.f/(1.f + expf(-h));
                Ab[row*PC + col] = acc[r][c] * s * (1.f + h*(1.f - s));
            }
    }
    __syncthreads();

    mmT(Ks, Ab, d_g0 + (size_t)chunk*DHq*DHq, tid);   // g0 = k^T @ dh
}

// ---------------- K7: double linear-recurrence scan over N ----------------
__global__ void __launch_bounds__(256) scan_kernel(const float* __restrict__ w0,
                                                   const float* __restrict__ w1)
{
    __shared__ float ams[Nq], dcs[Nq];
    int gid = blockIdx.x*256 + threadIdx.x;     // BH * 16384 threads
    int bh = gid >> 14;
    int e  = gid & 16383;
    if (threadIdx.x < Nq){
        ams[threadIdx.x] = d_am[(size_t)bh*Nq + threadIdx.x];
        dcs[threadIdx.x] = d_dc[(size_t)bh*Nq + threadIdx.x];
    }
    __syncthreads();
    float m0=0.f,u0=0.f,m1=0.f,u1=0.f;
    float wa = w0[e], wb = w1[e];
    size_t base = ((size_t)bh*Nq)*16384 + e;
    for (int n=0;n<Nq;n++){
        float a = ams[n], d = 1.f - dcs[n];
        size_t off = base + (size_t)n*16384;
        m0 = a*m0 - d_g0[off];  u0 = d*u0 + m0;  d_w0t[off] = wa + u0;
        m1 = a*m1 - d_g1[off];  u1 = d*u1 + m1;  d_w1t[off] = wb + u1;
    }
}

// ---------------- K8: per-chunk retrieve MLP + RMSNorm + gate ----------------
__global__ void __launch_bounds__(256) retrieve_kernel(const float* __restrict__ gamma)
{
    extern __shared__ float sm[];
    float* Qs = sm;               // 64*129  (q, later o)
    float* Hb = Qs + 64*PC;       // h / a
    float* Ws = Hb + 64*PC;       // 128*129
    int tid = threadIdx.x;
    int chunk = blockIdx.x;
    int bh = chunk >> 6, n = chunk & 63;
    int b = bh >> 2, h = bh & 3;

    const float* qg = d_quer + ((size_t)bh*Lq + n*Cq)*DHq;
    for (int idx=tid; idx<64*128; idx+=256){
        int r = idx>>7, d = idx&127;
        Qs[r*PC+d] = qg[idx];
    }
    const float* w0c = d_w0t + (size_t)chunk*DHq*DHq;
    for (int idx=tid; idx<128*128; idx+=256){
        int r = idx>>7, d = idx&127;
        Ws[r*PC+d] = w0c[idx];
    }
    __syncthreads();

    mm64(Qs, Ws, Hb, tid);                 // h = q @ w0_t
    __syncthreads();
    for (int idx=tid; idx<64*128; idx+=256){
        int r = idx>>7, d = idx&127;
        float hh = Hb[r*PC+d];
        Hb[r*PC+d] = hh / (1.f + expf(-hh));
    }
    __syncthreads();
    const float* w1c = d_w1t + (size_t)chunk*DHq*DHq;
    for (int idx=tid; idx<128*128; idx+=256){
        int r = idx>>7, d = idx&127;
        Ws[r*PC+d] = w1c[idx];
    }
    __syncthreads();

    mm64(Hb, Ws, Qs, tid);                 // o = a @ w1_t  (into Qs)
    __syncthreads();

    int lane = tid & 31, w = tid >> 5;
#pragma unroll
    for (int rr=0; rr<8; rr++){
        int row = w*8 + rr;
        float v0 = Qs[row*PC + lane];
        float v1 = Qs[row*PC + lane + 32];
        float v2 = Qs[row*PC + lane + 64];
        float v3 = Qs[row*PC + lane + 96];
        float ss = v0*v0 + v1*v1 + v2*v2 + v3*v3;
#pragma unroll
        for (int off=16;off;off>>=1) ss += __shfl_xor_sync(0xffffffffu, ss, off);
        float sc = rsqrtf(ss*(1.f/DHq) + EPSq);
        int t = n*Cq + row;
        float g = d_gatev[((size_t)b*Lq + t)*Hq + h];
        float* dst = d_comb + ((size_t)b*Lq + t)*DIMq + h*DHq;
        dst[lane     ] = v0*sc*(gamma[h*DHq + lane     ] + 1.f)*g;
        dst[lane + 32] = v1*sc*(gamma[h*DHq + lane + 32] + 1.f)*g;
        dst[lane + 64] = v2*sc*(gamma[h*DHq + lane + 64] + 1.f)*g;
        dst[lane + 96] = v3*sc*(gamma[h*DHq + lane + 96] + 1.f)*g;
    }
}

// ---------------- K9: empty-embed fill for first C-1 rows ----------------
__global__ void empty_fill_kernel(const float* __restrict__ emb, float* __restrict__ out)
{
    int gid = blockIdx.x*blockDim.x + threadIdx.x;
    int total = Bq*(Cq-1)*DIMq;
    if (gid >= total) return;
    int d = gid & (DIMq-1);
    int row = gid / DIMq;          // b*(C-1)+t
    int b = row / (Cq-1), t = row % (Cq-1);
    out[((size_t)b*Lq + t)*DIMq + d] = emb[d];
}

// ---------------- launch ----------------
extern "C" void kernel_launch(void* const* d_in, const int* in_sizes, int n_in,
                              void* d_out, int out_size)
{
    const float* seq      = (const float*)d_in[0];
    const float* ss       = (const float*)d_in[1];
    const float* rs       = (const float*)d_in[2];
    const float* w_q      = (const float*)d_in[3];
    const float* w_kv     = (const float*)d_in[4];
    const float* w_ada    = (const float*)d_in[5];
    const float* w_mom    = (const float*)d_in[6];
    const float* w_dec    = (const float*)d_in[7];
    const float* w0       = (const float*)d_in[8];
    const float* w1       = (const float*)d_in[9];
    const float* gamma    = (const float*)d_in[10];
    const float* w_gate   = (const float*)d_in[11];
    const float* w_comb   = (const float*)d_in[12];
    const float* emb      = (const float*)d_in[13];
    float* out = (float*)d_out;

    float *p_snorm, *p_qin, *p_keys, *p_vals, *p_quer, *p_lr, *p_gate, *p_comb;
    cudaGetSymbolAddress((void**)&p_snorm, d_s_norm);
    cudaGetSymbolAddress((void**)&p_qin,   d_qin);
    cudaGetSymbolAddress((void**)&p_keys,  d_keys);
    cudaGetSymbolAddress((void**)&p_vals,  d_vals);
    cudaGetSymbolAddress((void**)&p_quer,  d_quer);
    cudaGetSymbolAddress((void**)&p_lr,    d_lr);
    cudaGetSymbolAddress((void**)&p_gate,  d_gatev);
    cudaGetSymbolAddress((void**)&p_comb,  d_comb);

    const int SMEM_G = (4*64*PC + 128*PC + 64) * 4;   // 198400 B
    const int SMEM_R = (2*64*PC + 128*PC) * 4;        // 132096 B
    cudaFuncSetAttribute(chunk_grad_kernel, cudaFuncAttributeMaxDynamicSharedMemorySize, SMEM_G);
    cudaFuncSetAttribute(retrieve_kernel,   cudaFuncAttributeMaxDynamicSharedMemorySize, SMEM_R);

    // 1. rmsnorms
    norm_kernel<<<Bq*Lq, 128>>>(seq, ss, rs);
    // 2. shifted retrieve input
    shift_kernel<<<(Bq*Lq*DIMq + 255)/256, 256>>>();
    // 3. chunk means
    chunk_mean_kernel<<<Bq*Nq, 512>>>();
    // 4. lr / gate projections
    proj4_kernel<0><<<(Bq*Lq*32 + 255)/256, 256>>>(p_snorm, w_ada,  p_lr);
    proj4_kernel<1><<<(Bq*Lq*32 + 255)/256, 256>>>(p_qin,   w_gate, p_gate);
    // 5. ada_mom / decay
    momdec_kernel<<<(Bq*Nq*32 + 255)/256, 256>>>(w_mom, w_dec);
    // 6. kv projection (keys/vals head-major)
    sgemm_kernel<0><<<dim3((2*Hq*DHq)/64, (Bq*Lq)/128), 256>>>(p_snorm, w_kv, p_keys, p_vals, 2*Hq*DHq, DIMq);
    // 7. query projection
    sgemm_kernel<1><<<dim3((Hq*DHq)/64, (Bq*Lq)/128), 256>>>(p_qin, w_q, p_quer, nullptr, Hq*DHq, DIMq);
    // 8. per-chunk gradients
    chunk_grad_kernel<<<NCHUNK, 256, SMEM_G>>>(w0, w1);
    // 9. momentum + decay scans -> per-chunk weights
    scan_kernel<<<(BHq*16384)/256, 256>>>(w0, w1);
    // 10. retrieve MLP + multihead RMSNorm + gate
    retrieve_kernel<<<NCHUNK, 256, SMEM_R>>>(gamma);
    // 11. head combine (writes rows C-1..L-1 of output)
    sgemm_kernel<2><<<dim3(DIMq/64, (Bq*Lq)/128), 256>>>(p_comb, w_comb, out, nullptr, DIMq, DIMq);
    // 12. empty rows 0..C-2
    empty_fill_kernel<<<(Bq*(Cq-1)*DIMq + 255)/256, 256>>>(emb, out);
}

// round 2
// speedup vs baseline: 2.6711x; 2.6711x over previous
#include <cuda_runtime.h>
#include <cuda_bf16.h>
#include <math.h>
#include <stdint.h>

// ---------------- problem constants ----------------
#define Bq   2
#define Lq   4096
#define DIMq 512
#define Hq   4
#define DHq  128
#define Cq   64
#define Nq   64          // L / C
#define BHq  8           // B * H
#define NCHUNK 512       // BH * N
#define MAXLR 0.01f
#define EPSq  1e-6f

// ---------------- scratch (device globals; allocation-free) ----------------
__device__ float d_s_norm[Bq*Lq*DIMq];
__device__ float d_r_norm[Bq*Lq*DIMq];
__device__ float d_keys  [BHq*Lq*DHq];
__device__ float d_vals  [BHq*Lq*DHq];
__device__ float d_quer  [BHq*Lq*DHq];
__device__ float d_lr    [BHq*Lq];
__device__ float d_seqmean[Bq*Nq*DIMq];
__device__ float d_am    [BHq*Nq];
__device__ float d_dc    [BHq*Nq];
__device__ float d_g0    [NCHUNK*DHq*DHq];
__device__ float d_g1    [NCHUNK*DHq*DHq];
__device__ float d_w0t   [NCHUNK*DHq*DHq];
__device__ float d_w1t   [NCHUNK*DHq*DHq];
__device__ float d_comb  [Bq*Lq*DIMq];
__device__ float d_gatev [Bq*Lq*Hq];

__device__ __forceinline__ float sigm(float x){ return 1.f/(1.f+expf(-x)); }

// ---------------- tf32 mma primitives ----------------
__device__ __forceinline__ uint32_t f2tf32(float x){
    uint32_t r; asm("cvt.rna.tf32.f32 %0, %1;" : "=r"(r) : "f"(x)); return r;
}
__device__ __forceinline__ uint32_t ldtf(const float* p){ return f2tf32(*p); }
__device__ __forceinline__ uint32_t ldtf(const uint32_t* p){ return *p; }

__device__ __forceinline__ void mma8(float (&c)[4],
                                     uint32_t a0,uint32_t a1,uint32_t a2,uint32_t a3,
                                     uint32_t b0,uint32_t b1){
    asm volatile("mma.sync.aligned.m16n8k8.row.col.f32.tf32.tf32.f32 "
        "{%0,%1,%2,%3},{%4,%5,%6,%7},{%8,%9},{%0,%1,%2,%3};"
        : "+f"(c[0]),"+f"(c[1]),"+f"(c[2]),"+f"(c[3])
        : "r"(a0),"r"(a1),"r"(a2),"r"(a3),"r"(b0),"r"(b1));
}

// warp computes a (MT*16) x (NT*8) tile over KS k-steps of 8.
// ATr: 0 -> A(row,k)=A[row*ap+k]; 1 -> A(row,k)=A[k*ap+row]
// BTr: 0 -> B(k,n)=B[k*bp+n];     1 -> B(k,n)=B[n*bp+k]
template<int MT,int NT,int KS,int ATr,int BTr,class TA,class TB>
__device__ __forceinline__ void wtile(const TA* A,int ap,const TB* B,int bp,
                                      float (&acc)[MT][NT][4], int rbase,int cbase,int lane)
{
    int g = lane>>2, tg = lane&3;
#pragma unroll
    for (int ks=0;ks<KS;ks++){
        int k0 = ks*8 + tg;
        uint32_t af[MT][4];
#pragma unroll
        for (int mt=0;mt<MT;mt++){
            int r0 = rbase + mt*16 + g;
            if (ATr==0){
                af[mt][0]=ldtf(&A[r0*ap + k0]);
                af[mt][1]=ldtf(&A[(r0+8)*ap + k0]);
                af[mt][2]=ldtf(&A[r0*ap + k0+4]);
                af[mt][3]=ldtf(&A[(r0+8)*ap + k0+4]);
            } else {
                af[mt][0]=ldtf(&A[k0*ap + r0]);
                af[mt][1]=ldtf(&A[k0*ap + r0+8]);
                af[mt][2]=ldtf(&A[(k0+4)*ap + r0]);
                af[mt][3]=ldtf(&A[(k0+4)*ap + r0+8]);
            }
        }
        uint32_t bf[NT][2];
#pragma unroll
        for (int nt=0;nt<NT;nt++){
            int n = cbase + nt*8 + g;
            if (BTr==0){
                bf[nt][0]=ldtf(&B[k0*bp + n]);
                bf[nt][1]=ldtf(&B[(k0+4)*bp + n]);
            } else {
                bf[nt][0]=ldtf(&B[n*bp + k0]);
                bf[nt][1]=ldtf(&B[n*bp + k0+4]);
            }
        }
#pragma unroll
        for (int mt=0;mt<MT;mt++)
#pragma unroll
            for (int nt=0;nt<NT;nt++)
                mma8(acc[mt][nt], af[mt][0],af[mt][1],af[mt][2],af[mt][3],
                     bf[nt][0],bf[nt][1]);
    }
}

// ---------------- K1: per-token rmsnorm + fused lr/gate projections ----------------
__global__ void __launch_bounds__(128) norm_kernel(const float* __restrict__ seq,
                                                   const float* __restrict__ ss,
                                                   const float* __restrict__ rs,
                                                   const float* __restrict__ w_ada,
                                                   const float* __restrict__ w_gate)
{
    int token = blockIdx.x;              // b*L + t
    int tid = threadIdx.x;
    int lane = tid & 31, w = tid >> 5;
    const float* x = seq + (size_t)token*DIMq;
    float v[4]; float acc = 0.f;
#pragma unroll
    for (int i=0;i<4;i++){ v[i] = x[tid + 128*i]; acc += v[i]*v[i]; }
#pragma unroll
    for (int off=16;off;off>>=1) acc += __shfl_xor_sync(0xffffffffu, acc, off);
    __shared__ float red[4];
    __shared__ float red8[4][8];
    if (lane==0) red[w] = acc;
    __syncthreads();
    float tot = red[0]+red[1]+red[2]+red[3];
    float rms = rsqrtf(tot*(1.f/DIMq) + EPSq);
    float p[8] = {0,0,0,0,0,0,0,0};
#pragma unroll
    for (int i=0;i<4;i++){
        int d = tid + 128*i;
        float y = v[i]*rms;
        float ysv = y*ss[d], yrv = y*rs[d];
        d_s_norm[(size_t)token*DIMq + d] = ysv;
        d_r_norm[(size_t)token*DIMq + d] = yrv;
#pragma unroll
        for (int h=0;h<4;h++){
            p[h]   += ysv*w_ada [d*4+h];
            p[4+h] += yrv*w_gate[d*4+h];
        }
    }
#pragma unroll
    for (int h=0;h<8;h++)
#pragma unroll
        for (int off=16;off;off>>=1) p[h] += __shfl_xor_sync(0xffffffffu, p[h], off);
    if (lane==0)
#pragma unroll
        for (int h=0;h<8;h++) red8[w][h] = p[h];
    __syncthreads();
    if (tid < 8){
        float s = red8[0][tid]+red8[1][tid]+red8[2][tid]+red8[3][tid];
        int b = token >> 12, t = token & (Lq-1);
        if (tid < 4)
            d_lr[((size_t)(b*Hq+tid))*Lq + t] = sigm(s)*MAXLR;
        else if (t >= Cq-1)
            d_gatev[((size_t)b*Lq + (t-(Cq-1)))*Hq + (tid-4)] = sigm(s);
    }
}

// ---------------- K3: chunk means of s ----------------
__global__ void __launch_bounds__(512) chunk_mean_kernel()
{
    int bn = blockIdx.x;            // b*N + n
    int d = threadIdx.x;
    int b = bn / Nq, n = bn % Nq;
    const float* base = d_s_norm + ((size_t)b*Lq + n*Cq)*DIMq + d;
    float acc = 0.f;
#pragma unroll 8
    for (int c=0;c<Cq;c++) acc += base[(size_t)c*DIMq];
    d_seqmean[(size_t)bn*DIMq + d] = acc*(1.f/Cq);
}

// ---------------- K5: ada_mom / decay from seq_mean ----------------
__global__ void momdec_kernel(const float* __restrict__ wm, const float* __restrict__ wd)
{
    int warp = (blockIdx.x*blockDim.x + threadIdx.x) >> 5;
    int lane = threadIdx.x & 31;
    if (warp >= Bq*Nq) return;
    const float* x = d_seqmean + (size_t)warp*DIMq;
    float a[4]={0,0,0,0}, b4[4]={0,0,0,0};
    for (int d=lane; d<DIMq; d+=32){
        float xv = x[d];
#pragma unroll
        for (int h=0;h<4;h++){ a[h]+=xv*wm[d*4+h]; b4[h]+=xv*wd[d*4+h]; }
    }
#pragma unroll
    for (int off=16;off;off>>=1)
#pragma unroll
        for (int h=0;h<4;h++){
            a[h]  += __shfl_down_sync(0xffffffffu,a[h],off);
            b4[h] += __shfl_down_sync(0xffffffffu,b4[h],off);
        }
    if (lane==0){
        int b = warp / Nq, n = warp % Nq;
#pragma unroll
        for (int h=0;h<4;h++){
            d_am[(size_t)(b*Hq+h)*Nq + n] = sigm(a[h]);
            d_dc[(size_t)(b*Hq+h)*Nq + n] = sigm(b4[h]);
        }
    }
}

// ---------------- big GEMM, tf32 tensor cores, 128x64 tile ----------------
// MODE 0: keys/vals head-major (Nc=1024)
// MODE 1: A read shifted by C-1 from r_norm, out queries head-major (Nc=512)
// MODE 2: final combine -> out, shifted +C-1 store (Nc=512)
#define AP 36
#define BP 68
template<int MODE>
__global__ void __launch_bounds__(256) gemm_tc(const float* __restrict__ A,
                                               const float* __restrict__ W,
                                               float* __restrict__ out0,
                                               float* __restrict__ out1,
                                               int Nc, int K)
{
    __shared__ uint32_t As[128*AP];
    __shared__ uint32_t Bs[32*BP];
    int tid = threadIdx.x;
    int lane = tid & 31, wid = tid >> 5;
    int wm = wid >> 1, wn = wid & 1;       // 4 x 2 warps
    int m0 = blockIdx.y*128, n0 = blockIdx.x*64;
    float acc[2][4][4] = {};

    for (int k0=0;k0<K;k0+=32){
#pragma unroll
        for (int i=0;i<4;i++){
            int idx = tid + 256*i;         // 1024 float4s
            int r = idx >> 3, c4 = idx & 7;
            int gr = m0 + r;
            float4 val;
            if (MODE==1){
                int t = gr & (Lq-1);
                if (t <= Lq - Cq) val = *(const float4*)&A[(size_t)(gr+Cq-1)*K + k0 + c4*4];
                else val = make_float4(0.f,0.f,0.f,0.f);
            } else {
                val = *(const float4*)&A[(size_t)gr*K + k0 + c4*4];
            }
            uint32_t* dst = &As[r*AP + c4*4];
            dst[0]=f2tf32(val.x); dst[1]=f2tf32(val.y);
            dst[2]=f2tf32(val.z); dst[3]=f2tf32(val.w);
        }
#pragma unroll
        for (int i=0;i<2;i++){
            int idx = tid + 256*i;         // 512 float4s
            int r = idx >> 4, c4 = idx & 15;
            float4 val = *(const float4*)&W[(size_t)(k0+r)*Nc + n0 + c4*4];
            uint32_t* dst = &Bs[r*BP + c4*4];
            dst[0]=f2tf32(val.x); dst[1]=f2tf32(val.y);
            dst[2]=f2tf32(val.z); dst[3]=f2tf32(val.w);
        }
        __syncthreads();
        wtile<2,4,4,0,0>(As, AP, Bs, BP, acc, wm*32, wn*32, lane);
        __syncthreads();
    }
    int g = lane>>2, tg = lane&3;
#pragma unroll
    for (int mt=0;mt<2;mt++)
#pragma unroll
    for (int nt=0;nt<4;nt++)
#pragma unroll
    for (int e=0;e<4;e++){
        int row = m0 + wm*32 + mt*16 + g + ((e&2)?8:0);
        int col = n0 + wn*32 + nt*8 + 2*tg + (e&1);
        float v = acc[mt][nt][e];
        int b = row >> 12, t = row & (Lq-1);
        if (MODE==0){
            if (col < Hq*DHq){
                int h = col>>7, d = col&127;
                out0[((size_t)(b*Hq+h)*Lq + t)*DHq + d] = v;
            } else {
                int c2 = col - Hq*DHq; int h = c2>>7, d = c2&127;
                out1[((size_t)(b*Hq+h)*Lq + t)*DHq + d] = v;
            }
        } else if (MODE==1){
            int h = col>>7, d = col&127;
            out0[((size_t)(b*Hq+h)*Lq + t)*DHq + d] = v;
        } else {
            if (t <= Lq - Cq)
                out0[((size_t)b*Lq + t + Cq - 1)*DIMq + col] = v;
        }
    }
}

// ---------------- per-chunk kernels (smem pitch 132, conflict-free frags) ----------------
#define PC 132

// ---------------- K6: per-chunk gradient (all matmuls tf32 mma) ----------------
__global__ void __launch_bounds__(256) chunk_grad_kernel(const float* __restrict__ w0,
                                                         const float* __restrict__ w1)
{
    extern __shared__ float sm[];
    float* Ks = sm;               // 64*PC  keys
    float* Hb = Ks + 64*PC;       // h
    float* Ab = Hb + 64*PC;       // a=silu(h), later dh
    float* Db = Ab + 64*PC;       // v, later dpred
    float* Ws = Db + 64*PC;       // 128*PC (w0, then w1)
    float* Lr = Ws + 128*PC;      // 64
    int tid = threadIdx.x, lane = tid&31, wid = tid>>5;
    int wm = wid>>2, wn = wid&3;  // 2 x 4 warps
    int g = lane>>2, tg = lane&3;
    int chunk = blockIdx.x;
    int bh = chunk >> 6, t0 = (chunk & 63) << 6;

    const float4* kg = (const float4*)(d_keys + ((size_t)bh*Lq + t0)*DHq);
    const float4* vg = (const float4*)(d_vals + ((size_t)bh*Lq + t0)*DHq);
#pragma unroll
    for (int u=tid; u<2048; u+=256){
        int r = u>>5, c = (u&31)*4;
        float4 a = kg[u], b = vg[u];
        Ks[r*PC+c]=a.x; Ks[r*PC+c+1]=a.y; Ks[r*PC+c+2]=a.z; Ks[r*PC+c+3]=a.w;
        Db[r*PC+c]=b.x; Db[r*PC+c+1]=b.y; Db[r*PC+c+2]=b.z; Db[r*PC+c+3]=b.w;
    }
    if (tid < 64) Lr[tid] = d_lr[(size_t)bh*Lq + t0 + tid];
    const float4* w04 = (const float4*)w0;
#pragma unroll
    for (int u=tid; u<4096; u+=256){
        int r = u>>5, c = (u&31)*4;
        float4 a = w04[u];
        Ws[r*PC+c]=a.x; Ws[r*PC+c+1]=a.y; Ws[r*PC+c+2]=a.z; Ws[r*PC+c+3]=a.w;
    }
    __syncthreads();

    {   // h = K @ w0 ; store h and a=silu(h)
        float acc[2][4][4] = {};
        wtile<2,4,16,0,0>(Ks, PC, Ws, PC, acc, wm*32, wn*32, lane);
#pragma unroll
        for (int mt=0;mt<2;mt++)
#pragma unroll
        for (int nt=0;nt<4;nt++)
#pragma unroll
        for (int e=0;e<4;e++){
            int row = wm*32 + mt*16 + g + ((e&2)?8:0);
            int col = wn*32 + nt*8 + 2*tg + (e&1);
            float h = acc[mt][nt][e];
            Hb[row*PC+col] = h;
            Ab[row*PC+col] = h/(1.f+expf(-h));
        }
    }
    __syncthreads();
    const float4* w14 = (const float4*)w1;
#pragma unroll
    for (int u=tid; u<4096; u+=256){
        int r = u>>5, c = (u&31)*4;
        float4 a = w14[u];
        Ws[r*PC+c]=a.x; Ws[r*PC+c+1]=a.y; Ws[r*PC+c+2]=a.z; Ws[r*PC+c+3]=a.w;
    }
    __syncthreads();

    {   // pred = a @ w1 ; dpred = lr*2/DH * (pred - v) into Db
        float acc[2][4][4] = {};
        wtile<2,4,16,0,0>(Ab, PC, Ws, PC, acc, wm*32, wn*32, lane);
#pragma unroll
        for (int mt=0;mt<2;mt++)
#pragma unroll
        for (int nt=0;nt<4;nt++)
#pragma unroll
        for (int e=0;e<4;e++){
            int row = wm*32 + mt*16 + g + ((e&2)?8:0);
            int col = wn*32 + nt*8 + 2*tg + (e&1);
            float coef = Lr[row]*(2.f/DHq);
            Db[row*PC+col] = coef*(acc[mt][nt][e] - Db[row*PC+col]);
        }
    }
    __syncthreads();

    {   // g1 = a^T @ dpred -> gmem
        float acc[4][4][4] = {};
        wtile<4,4,8,1,0>(Ab, PC, Db, PC, acc, wm*64, wn*32, lane);
        float* G = d_g1 + (size_t)chunk*DHq*DHq;
#pragma unroll
        for (int mt=0;mt<4;mt++)
#pragma unroll
        for (int nt=0;nt<4;nt++){
            int row = wm*64 + mt*16 + g;
            int col = wn*32 + nt*8 + 2*tg;
            *(float2*)&G[row*DHq + col]     = make_float2(acc[mt][nt][0], acc[mt][nt][1]);
            *(float2*)&G[(row+8)*DHq + col] = make_float2(acc[mt][nt][2], acc[mt][nt][3]);
        }
    }
    __syncthreads();

    {   // da = dpred @ w1^T ; dh = da * dsilu(h) into Ab
        float acc[2][4][4] = {};
        wtile<2,4,16,0,1>(Db, PC, Ws, PC, acc, wm*32, wn*32, lane);
#pragma unroll
        for (int mt=0;mt<2;mt++)
#pragma unroll
        for (int nt=0;nt<4;nt++)
#pragma unroll
        for (int e=0;e<4;e++){
            int row = wm*32 + mt*16 + g + ((e&2)?8:0);
            int col = wn*32 + nt*8 + 2*tg + (e&1);
            float h = Hb[row*PC+col];
            float s = 1.f/(1.f+expf(-h));
            Ab[row*PC+col] = acc[mt][nt][e] * s * (1.f + h*(1.f - s));
        }
    }
    __syncthreads();

    {   // g0 = K^T @ dh -> gmem
        float acc[4][4][4] = {};
        wtile<4,4,8,1,0>(Ks, PC, Ab, PC, acc, wm*64, wn*32, lane);
        float* G = d_g0 + (size_t)chunk*DHq*DHq;
#pragma unroll
        for (int mt=0;mt<4;mt++)
#pragma unroll
        for (int nt=0;nt<4;nt++){
            int row = wm*64 + mt*16 + g;
            int col = wn*32 + nt*8 + 2*tg;
            *(float2*)&G[row*DHq + col]     = make_float2(acc[mt][nt][0], acc[mt][nt][1]);
            *(float2*)&G[(row+8)*DHq + col] = make_float2(acc[mt][nt][2], acc[mt][nt][3]);
        }
    }
}

// ---------------- K7: double linear-recurrence scan over N ----------------
__global__ void __launch_bounds__(256) scan_kernel(const float* __restrict__ w0,
                                                   const float* __restrict__ w1)
{
    __shared__ float ams[Nq], dcs[Nq];
    int gid = blockIdx.x*256 + threadIdx.x;     // BH * 16384 threads
    int bh = gid >> 14;
    int e  = gid & 16383;
    if (threadIdx.x < Nq){
        ams[threadIdx.x] = d_am[(size_t)bh*Nq + threadIdx.x];
        dcs[threadIdx.x] = d_dc[(size_t)bh*Nq + threadIdx.x];
    }
    __syncthreads();
    float m0=0.f,u0=0.f,m1=0.f,u1=0.f;
    float wa = w0[e], wb = w1[e];
    size_t base = ((size_t)bh*Nq)*16384 + e;
    for (int n=0;n<Nq;n++){
        float a = ams[n], d = 1.f - dcs[n];
        size_t off = base + (size_t)n*16384;
        m0 = a*m0 - d_g0[off];  u0 = d*u0 + m0;  d_w0t[off] = wa + u0;
        m1 = a*m1 - d_g1[off];  u1 = d*u1 + m1;  d_w1t[off] = wb + u1;
    }
}

// ---------------- K8: per-chunk retrieve MLP + RMSNorm + gate ----------------
__global__ void __launch_bounds__(256) retrieve_kernel(const float* __restrict__ gamma)
{
    extern __shared__ float sm[];
    float* Qs = sm;               // 64*PC  (q, later o)
    float* Hb = Qs + 64*PC;       // a
    float* Ws = Hb + 64*PC;       // 128*PC
    int tid = threadIdx.x, lane = tid&31, wid = tid>>5;
    int wm = wid>>2, wn = wid&3;
    int g = lane>>2, tg = lane&3;
    int chunk = blockIdx.x;
    int bh = chunk >> 6, n = chunk & 63;
    int b = bh >> 2, h = bh & 3;

    const float4* qg = (const float4*)(d_quer + ((size_t)bh*Lq + n*Cq)*DHq);
#pragma unroll
    for (int u=tid; u<2048; u+=256){
        int r = u>>5, c = (u&31)*4;
        float4 a = qg[u];
        Qs[r*PC+c]=a.x; Qs[r*PC+c+1]=a.y; Qs[r*PC+c+2]=a.z; Qs[r*PC+c+3]=a.w;
    }
    const float4* w0c = (const float4*)(d_w0t + (size_t)chunk*DHq*DHq);
#pragma unroll
    for (int u=tid; u<4096; u+=256){
        int r = u>>5, c = (u&31)*4;
        float4 a = w0c[u];
        Ws[r*PC+c]=a.x; Ws[r*PC+c+1]=a.y; Ws[r*PC+c+2]=a.z; Ws[r*PC+c+3]=a.w;
    }
    __syncthreads();

    {   // a = silu(q @ w0_t)
        float acc[2][4][4] = {};
        wtile<2,4,16,0,0>(Qs, PC, Ws, PC, acc, wm*32, wn*32, lane);
#pragma unroll
        for (int mt=0;mt<2;mt++)
#pragma unroll
        for (int nt=0;nt<4;nt++)
#pragma unroll
        for (int e=0;e<4;e++){
            int row = wm*32 + mt*16 + g + ((e&2)?8:0);
            int col = wn*32 + nt*8 + 2*tg + (e&1);
            float hh = acc[mt][nt][e];
            Hb[row*PC+col] = hh/(1.f+expf(-hh));
        }
    }
    __syncthreads();
    const float4* w1c = (const float4*)(d_w1t + (size_t)chunk*DHq*DHq);
#pragma unroll
    for (int u=tid; u<4096; u+=256){
        int r = u>>5, c = (u&31)*4;
        float4 a = w1c[u];
        Ws[r*PC+c]=a.x; Ws[r*PC+c+1]=a.y; Ws[r*PC+c+2]=a.z; Ws[r*PC+c+3]=a.w;
    }
    __syncthreads();

    {   // o = a @ w1_t into Qs
        float acc[2][4][4] = {};
        wtile<2,4,16,0,0>(Hb, PC, Ws, PC, acc, wm*32, wn*32, lane);
#pragma unroll
        for (int mt=0;mt<2;mt++)
#pragma unroll
        for (int nt=0;nt<4;nt++)
#pragma unroll
        for (int e=0;e<4;e++){
            int row = wm*32 + mt*16 + g + ((e&2)?8:0);
            int col = wn*32 + nt*8 + 2*tg + (e&1);
            Qs[row*PC+col] = acc[mt][nt][e];
        }
    }
    __syncthreads();

    int w = tid >> 5;
#pragma unroll
    for (int rr=0; rr<8; rr++){
        int row = w*8 + rr;
        float v0 = Qs[row*PC + lane];
        float v1 = Qs[row*PC + lane + 32];
        float v2 = Qs[row*PC + lane + 64];
        float v3 = Qs[row*PC + lane + 96];
        float ss = v0*v0 + v1*v1 + v2*v2 + v3*v3;
#pragma unroll
        for (int off=16;off;off>>=1) ss += __shfl_xor_sync(0xffffffffu, ss, off);
        float sc = rsqrtf(ss*(1.f/DHq) + EPSq);
        int t = n*Cq + row;
        float gt = d_gatev[((size_t)b*Lq + t)*Hq + h];
        float* dst = d_comb + ((size_t)b*Lq + t)*DIMq + h*DHq;
        dst[lane     ] = v0*sc*(gamma[h*DHq + lane     ] + 1.f)*gt;
        dst[lane + 32] = v1*sc*(gamma[h*DHq + lane + 32] + 1.f)*gt;
        dst[lane + 64] = v2*sc*(gamma[h*DHq + lane + 64] + 1.f)*gt;
        dst[lane + 96] = v3*sc*(gamma[h*DHq + lane + 96] + 1.f)*gt;
    }
}

// ---------------- K9: empty-embed fill for first C-1 rows ----------------
__global__ void empty_fill_kernel(const float* __restrict__ emb, float* __restrict__ out)
{
    int gid = blockIdx.x*blockDim.x + threadIdx.x;
    int total = Bq*(Cq-1)*DIMq;
    if (gid >= total) return;
    int d = gid & (DIMq-1);
    int row = gid / DIMq;          // b*(C-1)+t
    int b = row / (Cq-1), t = row % (Cq-1);
    out[((size_t)b*Lq + t)*DIMq + d] = emb[d];
}

// ---------------- launch ----------------
extern "C" void kernel_launch(void* const* d_in, const int* in_sizes, int n_in,
                              void* d_out, int out_size)
{
    const float* seq      = (const float*)d_in[0];
    const float* ss       = (const float*)d_in[1];
    const float* rs       = (const float*)d_in[2];
    const float* w_q      = (const float*)d_in[3];
    const float* w_kv     = (const float*)d_in[4];
    const float* w_ada    = (const float*)d_in[5];
    const float* w_mom    = (const float*)d_in[6];
    const float* w_dec    = (const float*)d_in[7];
    const float* w0       = (const float*)d_in[8];
    const float* w1       = (const float*)d_in[9];
    const float* gamma    = (const float*)d_in[10];
    const float* w_gate   = (const float*)d_in[11];
    const float* w_comb   = (const float*)d_in[12];
    const float* emb      = (const float*)d_in[13];
    float* out = (float*)d_out;

    float *p_snorm, *p_rnorm, *p_keys, *p_vals, *p_quer, *p_comb;
    cudaGetSymbolAddress((void**)&p_snorm, d_s_norm);
    cudaGetSymbolAddress((void**)&p_rnorm, d_r_norm);
    cudaGetSymbolAddress((void**)&p_keys,  d_keys);
    cudaGetSymbolAddress((void**)&p_vals,  d_vals);
    cudaGetSymbolAddress((void**)&p_quer,  d_quer);
    cudaGetSymbolAddress((void**)&p_comb,  d_comb);

    const int SMEM_G = (4*64*PC + 128*PC + 64) * 4;   // 203008 B
    const int SMEM_R = (2*64*PC + 128*PC) * 4;        // 135168 B
    cudaFuncSetAttribute(chunk_grad_kernel, cudaFuncAttributeMaxDynamicSharedMemorySize, SMEM_G);
    cudaFuncSetAttribute(retrieve_kernel,   cudaFuncAttributeMaxDynamicSharedMemorySize, SMEM_R);

    // 1. rmsnorms + fused lr/gate projections
    norm_kernel<<<Bq*Lq, 128>>>(seq, ss, rs, w_ada, w_gate);
    // 2. chunk means
    chunk_mean_kernel<<<Bq*Nq, 512>>>();
    // 3. ada_mom / decay
    momdec_kernel<<<(Bq*Nq*32 + 255)/256, 256>>>(w_mom, w_dec);
    // 4. kv projection (keys/vals head-major), tf32 TC
    gemm_tc<0><<<dim3((2*Hq*DHq)/64, (Bq*Lq)/128), 256>>>(p_snorm, w_kv, p_keys, p_vals, 2*Hq*DHq, DIMq);
    // 5. query projection (reads r_norm shifted), tf32 TC
    gemm_tc<1><<<dim3((Hq*DHq)/64, (Bq*Lq)/128), 256>>>(p_rnorm, w_q, p_quer, nullptr, Hq*DHq, DIMq);
    // 6. per-chunk gradients (tf32 TC)
    chunk_grad_kernel<<<NCHUNK, 256, SMEM_G>>>(w0, w1);
    // 7. momentum + decay scans -> per-chunk weights
    scan_kernel<<<(BHq*16384)/256, 256>>>(w0, w1);
    // 8. retrieve MLP + multihead RMSNorm + gate (tf32 TC)
    retrieve_kernel<<<NCHUNK, 256, SMEM_R>>>(gamma);
    // 9. head combine (writes rows C-1..L-1 of output), tf32 TC
    gemm_tc<2><<<dim3(DIMq/64, (Bq*Lq)/128), 256>>>(p_comb, w_comb, out, nullptr, DIMq, DIMq);
    // 10. empty rows 0..C-2
    empty_fill_kernel<<<(Bq*(Cq-1)*DIMq + 255)/256, 256>>>(emb, out);
}

// round 3
// speedup vs baseline: 2.7351x; 1.0240x over previous
#include <cuda_runtime.h>
#include <cuda_bf16.h>
#include <math.h>
#include <stdint.h>

// ---------------- problem constants ----------------
#define Bq   2
#define Lq   4096
#define DIMq 512
#define Hq   4
#define DHq  128
#define Cq   64
#define Nq   64          // L / C
#define BHq  8           // B * H
#define NCHUNK 512       // BH * N
#define MAXLR 0.01f
#define EPSq  1e-6f

// ---------------- scratch (device globals; allocation-free) ----------------
__device__ float d_s_norm[Bq*Lq*DIMq];
__device__ float d_r_norm[Bq*Lq*DIMq];
__device__ float d_keys  [BHq*Lq*DHq];
__device__ float d_vals  [BHq*Lq*DHq];
__device__ float d_quer  [BHq*Lq*DHq];
__device__ float d_lr    [BHq*Lq];
__device__ float d_seqmean[Bq*Nq*DIMq];
__device__ float d_am    [BHq*Nq];
__device__ float d_dc    [BHq*Nq];
__device__ float d_g0    [NCHUNK*DHq*DHq];
__device__ float d_g1    [NCHUNK*DHq*DHq];
__device__ float d_w0t   [NCHUNK*DHq*DHq];
__device__ float d_w1t   [NCHUNK*DHq*DHq];
__device__ float d_comb  [Bq*Lq*DIMq];
__device__ float d_gatev [Bq*Lq*Hq];

__device__ __forceinline__ float sigm(float x){ return 1.f/(1.f+expf(-x)); }

// ---------------- tf32 mma primitives ----------------
__device__ __forceinline__ uint32_t f2tf32(float x){
    uint32_t r; asm("cvt.rna.tf32.f32 %0, %1;" : "=r"(r) : "f"(x)); return r;
}
__device__ __forceinline__ uint32_t ldtf(const float* p){ return f2tf32(*p); }
__device__ __forceinline__ uint32_t ldtf(const uint32_t* p){ return *p; }

__device__ __forceinline__ void mma8(float (&c)[4],
                                     uint32_t a0,uint32_t a1,uint32_t a2,uint32_t a3,
                                     uint32_t b0,uint32_t b1){
    asm volatile("mma.sync.aligned.m16n8k8.row.col.f32.tf32.tf32.f32 "
        "{%0,%1,%2,%3},{%4,%5,%6,%7},{%8,%9},{%0,%1,%2,%3};"
        : "+f"(c[0]),"+f"(c[1]),"+f"(c[2]),"+f"(c[3])
        : "r"(a0),"r"(a1),"r"(a2),"r"(a3),"r"(b0),"r"(b1));
}

__device__ __forceinline__ void ldsm4(uint32_t* r, uint32_t addr){
    asm volatile("ldmatrix.sync.aligned.m8n8.x4.shared.b16 {%0,%1,%2,%3}, [%4];"
        : "=r"(r[0]),"=r"(r[1]),"=r"(r[2]),"=r"(r[3]) : "r"(addr));
}

// per-warp ldmatrix base address for A fragments at row-block rbase
__device__ __forceinline__ uint32_t ldsmBase(const uint32_t* arr, int rbase, int ap, int lane){
    return (uint32_t)__cvta_generic_to_shared(arr)
         + (uint32_t)(((rbase + (lane&15))*ap + ((lane>>4)<<2))*4);
}

// warp tile with ldmatrix A-side. A fragment rows baked into aByte.
// BTr: 0 -> B(k,n)=B[k*bp+n];  1 -> B(k,n)=B[n*bp+k]
template<int MT,int NT,int KS,int BTr>
__device__ __forceinline__ void wtileLA(uint32_t aByte, int ap, const uint32_t* B, int bp,
                                        float (&acc)[MT][NT][4], int cbase, int lane)
{
    int g = lane>>2, tg = lane&3;
#pragma unroll
    for (int ks=0;ks<KS;ks++){
        int k0 = ks*8;
        uint32_t af[MT][4];
#pragma unroll
        for (int mt=0;mt<MT;mt++)
            ldsm4(af[mt], aByte + (uint32_t)((mt*16*ap + k0)*4));
        uint32_t bf[NT][2];
#pragma unroll
        for (int nt=0;nt<NT;nt++){
            int n = cbase + nt*8 + g;
            if (BTr==0){
                bf[nt][0] = B[(k0+tg)*bp + n];
                bf[nt][1] = B[(k0+tg+4)*bp + n];
            } else {
                bf[nt][0] = B[n*bp + k0+tg];
                bf[nt][1] = B[n*bp + k0+tg+4];
            }
        }
#pragma unroll
        for (int mt=0;mt<MT;mt++)
#pragma unroll
            for (int nt=0;nt<NT;nt++)
                mma8(acc[mt][nt], af[mt][0],af[mt][1],af[mt][2],af[mt][3],
                     bf[nt][0],bf[nt][1]);
    }
}

// scalar warp tile (for transposed-A ops)
template<int MT,int NT,int KS,int ATr,int BTr,class TA,class TB>
__device__ __forceinline__ void wtileS(const TA* A,int ap,const TB* B,int bp,
                                       float (&acc)[MT][NT][4], int rbase,int cbase,int lane)
{
    int g = lane>>2, tg = lane&3;
#pragma unroll
    for (int ks=0;ks<KS;ks++){
        int k0 = ks*8 + tg;
        uint32_t af[MT][4];
#pragma unroll
        for (int mt=0;mt<MT;mt++){
            int r0 = rbase + mt*16 + g;
            if (ATr==0){
                af[mt][0]=ldtf(&A[r0*ap + k0]);
                af[mt][1]=ldtf(&A[(r0+8)*ap + k0]);
                af[mt][2]=ldtf(&A[r0*ap + k0+4]);
                af[mt][3]=ldtf(&A[(r0+8)*ap + k0+4]);
            } else {
                af[mt][0]=ldtf(&A[k0*ap + r0]);
                af[mt][1]=ldtf(&A[k0*ap + r0+8]);
                af[mt][2]=ldtf(&A[(k0+4)*ap + r0]);
                af[mt][3]=ldtf(&A[(k0+4)*ap + r0+8]);
            }
        }
        uint32_t bf[NT][2];
#pragma unroll
        for (int nt=0;nt<NT;nt++){
            int n = cbase + nt*8 + g;
            if (BTr==0){
                bf[nt][0]=ldtf(&B[k0*bp + n]);
                bf[nt][1]=ldtf(&B[(k0+4)*bp + n]);
            } else {
                bf[nt][0]=ldtf(&B[n*bp + k0]);
                bf[nt][1]=ldtf(&B[n*bp + k0+4]);
            }
        }
#pragma unroll
        for (int mt=0;mt<MT;mt++)
#pragma unroll
            for (int nt=0;nt<NT;nt++)
                mma8(acc[mt][nt], af[mt][0],af[mt][1],af[mt][2],af[mt][3],
                     bf[nt][0],bf[nt][1]);
    }
}

// ---------------- K1: per-token rmsnorm + fused lr/gate projections ----------------
__global__ void __launch_bounds__(128) norm_kernel(const float* __restrict__ seq,
                                                   const float* __restrict__ ss,
                                                   const float* __restrict__ rs,
                                                   const float* __restrict__ w_ada,
                                                   const float* __restrict__ w_gate)
{
    int token = blockIdx.x;              // b*L + t
    int tid = threadIdx.x;
    int lane = tid & 31, w = tid >> 5;
    const float* x = seq + (size_t)token*DIMq;
    float v[4]; float acc = 0.f;
#pragma unroll
    for (int i=0;i<4;i++){ v[i] = x[tid + 128*i]; acc += v[i]*v[i]; }
#pragma unroll
    for (int off=16;off;off>>=1) acc += __shfl_xor_sync(0xffffffffu, acc, off);
    __shared__ float red[4];
    __shared__ float red8[4][8];
    if (lane==0) red[w] = acc;
    __syncthreads();
    float tot = red[0]+red[1]+red[2]+red[3];
    float rms = rsqrtf(tot*(1.f/DIMq) + EPSq);
    float p[8] = {0,0,0,0,0,0,0,0};
#pragma unroll
    for (int i=0;i<4;i++){
        int d = tid + 128*i;
        float y = v[i]*rms;
        float ysv = y*ss[d], yrv = y*rs[d];
        d_s_norm[(size_t)token*DIMq + d] = ysv;
        d_r_norm[(size_t)token*DIMq + d] = yrv;
#pragma unroll
        for (int h=0;h<4;h++){
            p[h]   += ysv*w_ada [d*4+h];
            p[4+h] += yrv*w_gate[d*4+h];
        }
    }
#pragma unroll
    for (int h=0;h<8;h++)
#pragma unroll
        for (int off=16;off;off>>=1) p[h] += __shfl_xor_sync(0xffffffffu, p[h], off);
    if (lane==0)
#pragma unroll
        for (int h=0;h<8;h++) red8[w][h] = p[h];
    __syncthreads();
    if (tid < 8){
        float s = red8[0][tid]+red8[1][tid]+red8[2][tid]+red8[3][tid];
        int b = token >> 12, t = token & (Lq-1);
        if (tid < 4)
            d_lr[((size_t)(b*Hq+tid))*Lq + t] = sigm(s)*MAXLR;
        else if (t >= Cq-1)
            d_gatev[((size_t)b*Lq + (t-(Cq-1)))*Hq + (tid-4)] = sigm(s);
    }
}

// ---------------- K3: chunk means of s ----------------
__global__ void __launch_bounds__(512) chunk_mean_kernel()
{
    int bn = blockIdx.x;            // b*N + n
    int d = threadIdx.x;
    int b = bn / Nq, n = bn % Nq;
    const float* base = d_s_norm + ((size_t)b*Lq + n*Cq)*DIMq + d;
    float acc = 0.f;
#pragma unroll 8
    for (int c=0;c<Cq;c++) acc += base[(size_t)c*DIMq];
    d_seqmean[(size_t)bn*DIMq + d] = acc*(1.f/Cq);
}

// ---------------- K5: ada_mom / decay from seq_mean ----------------
__global__ void momdec_kernel(const float* __restrict__ wm, const float* __restrict__ wd)
{
    int warp = (blockIdx.x*blockDim.x + threadIdx.x) >> 5;
    int lane = threadIdx.x & 31;
    if (warp >= Bq*Nq) return;
    const float* x = d_seqmean + (size_t)warp*DIMq;
    float a[4]={0,0,0,0}, b4[4]={0,0,0,0};
    for (int d=lane; d<DIMq; d+=32){
        float xv = x[d];
#pragma unroll
        for (int h=0;h<4;h++){ a[h]+=xv*wm[d*4+h]; b4[h]+=xv*wd[d*4+h]; }
    }
#pragma unroll
    for (int off=16;off;off>>=1)
#pragma unroll
        for (int h=0;h<4;h++){
            a[h]  += __shfl_down_sync(0xffffffffu,a[h],off);
            b4[h] += __shfl_down_sync(0xffffffffu,b4[h],off);
        }
    if (lane==0){
        int b = warp / Nq, n = warp % Nq;
#pragma unroll
        for (int h=0;h<4;h++){
            d_am[(size_t)(b*Hq+h)*Nq + n] = sigm(a[h]);
            d_dc[(size_t)(b*Hq+h)*Nq + n] = sigm(b4[h]);
        }
    }
}

// ---------------- big GEMM, tf32 TC, ldmatrix-A, double-buffered ----------------
// MODE 0: keys/vals head-major (Nc=1024)
// MODE 1: A read shifted by C-1 from r_norm, out queries head-major (Nc=512)
// MODE 2: final combine -> out, shifted +C-1 store (Nc=512)
#define GAP 36
#define GBP 72
template<int MODE>
__global__ void __launch_bounds__(256) gemm_tc(const float* __restrict__ A,
                                               const float* __restrict__ W,
                                               float* __restrict__ out0,
                                               float* __restrict__ out1,
                                               int Nc, int K)
{
    extern __shared__ uint32_t sh[];
    uint32_t* Asb[2] = { sh, sh + 128*GAP };
    uint32_t* Bsb[2] = { sh + 2*128*GAP, sh + 2*128*GAP + 32*GBP };
    int tid = threadIdx.x, lane = tid & 31, wid = tid >> 5;
    int wm = wid >> 1, wn = wid & 1;       // 4 x 2 warps, 32x32 tiles
    int m0 = blockIdx.y*128, n0 = blockIdx.x*64;
    float acc[2][4][4] = {};
    int ar = tid>>3, ac4 = tid&7;          // A loads: rows ar+32i
    int br = tid>>4, bc4 = tid&15;         // B loads: rows br+16i
    float4 ra[4], rb[2];

    const int NK = K/32;
#pragma unroll 1
    for (int kt=-1; kt<NK; kt++){
        if (kt+1 < NK){                    // prefetch tile kt+1
            int k0 = (kt+1)*32;
#pragma unroll
            for (int i=0;i<4;i++){
                int gr = m0 + ar + 32*i;
                if (MODE==1){
                    int t = gr & (Lq-1);
                    ra[i] = (t <= Lq-Cq) ? *(const float4*)&A[(size_t)(gr+Cq-1)*K + k0 + ac4*4]
                                         : make_float4(0.f,0.f,0.f,0.f);
                } else ra[i] = *(const float4*)&A[(size_t)gr*K + k0 + ac4*4];
            }
#pragma unroll
            for (int i=0;i<2;i++)
                rb[i] = *(const float4*)&W[(size_t)(k0 + br + 16*i)*Nc + n0 + bc4*4];
        }
        if (kt >= 0){                      // compute on buffer kt&1
            int b = kt&1;
            uint32_t aB = ldsmBase(Asb[b], wm*32, GAP, lane);
            wtileLA<2,4,4,0>(aB, GAP, Bsb[b], GBP, acc, wn*32, lane);
            __syncthreads();
        }
        if (kt+1 < NK){                    // store prefetched tile
            int b = (kt+1)&1;
#pragma unroll
            for (int i=0;i<4;i++)
                *(uint4*)&Asb[b][(ar+32*i)*GAP + ac4*4] =
                    make_uint4(f2tf32(ra[i].x),f2tf32(ra[i].y),f2tf32(ra[i].z),f2tf32(ra[i].w));
#pragma unroll
            for (int i=0;i<2;i++)
                *(uint4*)&Bsb[b][(br+16*i)*GBP + bc4*4] =
                    make_uint4(f2tf32(rb[i].x),f2tf32(rb[i].y),f2tf32(rb[i].z),f2tf32(rb[i].w));
            __syncthreads();
        }
    }

    int g = lane>>2, tg = lane&3;
#pragma unroll
    for (int mt=0;mt<2;mt++)
#pragma unroll
    for (int nt=0;nt<4;nt++)
#pragma unroll
    for (int e=0;e<4;e++){
        int row = m0 + wm*32 + mt*16 + g + ((e&2)?8:0);
        int col = n0 + wn*32 + nt*8 + 2*tg + (e&1);
        float v = acc[mt][nt][e];
        int b = row >> 12, t = row & (Lq-1);
        if (MODE==0){
            if (col < Hq*DHq){
                int h = col>>7, d = col&127;
                out0[((size_t)(b*Hq+h)*Lq + t)*DHq + d] = v;
            } else {
                int c2 = col - Hq*DHq; int h = c2>>7, d = c2&127;
                out1[((size_t)(b*Hq+h)*Lq + t)*DHq + d] = v;
            }
        } else if (MODE==1){
            int h = col>>7, d = col&127;
            out0[((size_t)(b*Hq+h)*Lq + t)*DHq + d] = v;
        } else {
            if (t <= Lq - Cq)
                out0[((size_t)b*Lq + t + Cq - 1)*DIMq + col] = v;
        }
    }
}

// ---------------- per-chunk kernels ----------------
#define PT 132   // pitch for 64-row t-major tiles (ldmatrix-friendly: 132%8==4)
#define PW 136   // pitch for 128-row weight tiles (scalar B conflict-free: 136%32==8)

// ---------------- K6: per-chunk gradient ----------------
__global__ void __launch_bounds__(256) chunk_grad_kernel(const float* __restrict__ w0,
                                                         const float* __restrict__ w1)
{
    extern __shared__ uint32_t smu[];
    uint32_t* Ks = smu;            // 64*PT  keys (tf32)
    uint32_t* Ab = Ks + 64*PT;     // a=silu(h) (tf32), later dh
    uint32_t* Db = Ab + 64*PT;     // v (raw fp32), later dpred (tf32)
    uint32_t* Ws = Db + 64*PT;     // 128*PW (w0, then w1) tf32
    float* Lr = (float*)(Ws + 128*PW); // 64
    int tid = threadIdx.x, lane = tid&31, wid = tid>>5;
    int wm = wid>>2, wn = wid&3;   // 2 x 4 warps
    int g = lane>>2, tg = lane&3;
    int chunk = blockIdx.x;
    int bh = chunk >> 6, t0 = (chunk & 63) << 6;

    const float4* kg = (const float4*)(d_keys + ((size_t)bh*Lq + t0)*DHq);
    const float4* vg = (const float4*)(d_vals + ((size_t)bh*Lq + t0)*DHq);
#pragma unroll
    for (int u=tid; u<2048; u+=256){
        int r = u>>5, c = (u&31)*4;
        float4 a = kg[u], b = vg[u];
        *(uint4*)&Ks[r*PT+c] = make_uint4(f2tf32(a.x),f2tf32(a.y),f2tf32(a.z),f2tf32(a.w));
        *(uint4*)&Db[r*PT+c] = make_uint4(__float_as_uint(b.x),__float_as_uint(b.y),
                                          __float_as_uint(b.z),__float_as_uint(b.w));
    }
    if (tid < 64) Lr[tid] = d_lr[(size_t)bh*Lq + t0 + tid];
    const float4* w04 = (const float4*)w0;
#pragma unroll
    for (int u=tid; u<4096; u+=256){
        int r = u>>5, c = (u&31)*4;
        float4 a = w04[u];
        *(uint4*)&Ws[r*PW+c] = make_uint4(f2tf32(a.x),f2tf32(a.y),f2tf32(a.z),f2tf32(a.w));
    }
    __syncthreads();

    // h = K @ w0 (h kept in registers); a = silu(h) -> Ab
    float hreg[2][4][4] = {};
    wtileLA<2,4,16,0>(ldsmBase(Ks, wm*32, PT, lane), PT, Ws, PW, hreg, wn*32, lane);
#pragma unroll
    for (int mt=0;mt<2;mt++)
#pragma unroll
    for (int nt=0;nt<4;nt++)
#pragma unroll
    for (int e=0;e<4;e++){
        int row = wm*32 + mt*16 + g + ((e&2)?8:0);
        int col = wn*32 + nt*8 + 2*tg + (e&1);
        float h = hreg[mt][nt][e];
        Ab[row*PT+col] = f2tf32(h/(1.f+expf(-h)));
    }
    __syncthreads();
    const float4* w14 = (const float4*)w1;
#pragma unroll
    for (int u=tid; u<4096; u+=256){
        int r = u>>5, c = (u&31)*4;
        float4 a = w14[u];
        *(uint4*)&Ws[r*PW+c] = make_uint4(f2tf32(a.x),f2tf32(a.y),f2tf32(a.z),f2tf32(a.w));
    }
    __syncthreads();

    {   // pred = a @ w1 ; dpred = lr*2/DH * (pred - v) into Db (tf32)
        float acc[2][4][4] = {};
        wtileLA<2,4,16,0>(ldsmBase(Ab, wm*32, PT, lane), PT, Ws, PW, acc, wn*32, lane);
#pragma unroll
        for (int mt=0;mt<2;mt++)
#pragma unroll
        for (int nt=0;nt<4;nt++)
#pragma unroll
        for (int e=0;e<4;e++){
            int row = wm*32 + mt*16 + g + ((e&2)?8:0);
            int col = wn*32 + nt*8 + 2*tg + (e&1);
            float v = __uint_as_float(Db[row*PT+col]);
            Db[row*PT+col] = f2tf32(Lr[row]*(2.f/DHq)*(acc[mt][nt][e] - v));
        }
    }
    __syncthreads();

    {   // g1 = a^T @ dpred -> gmem
        float acc[4][4][4] = {};
        wtileS<4,4,8,1,0>(Ab, PT, Db, PT, acc, wm*64, wn*32, lane);
        float* G = d_g1 + (size_t)chunk*DHq*DHq;
#pragma unroll
        for (int mt=0;mt<4;mt++)
#pragma unroll
        for (int nt=0;nt<4;nt++){
            int row = wm*64 + mt*16 + g;
            int col = wn*32 + nt*8 + 2*tg;
            *(float2*)&G[row*DHq + col]     = make_float2(acc[mt][nt][0], acc[mt][nt][1]);
            *(float2*)&G[(row+8)*DHq + col] = make_float2(acc[mt][nt][2], acc[mt][nt][3]);
        }
    }
    __syncthreads();

    {   // da = dpred @ w1^T ; dh = da * dsilu(h_reg) into Ab (tf32)
        float acc[2][4][4] = {};
        wtileLA<2,4,16,1>(ldsmBase(Db, wm*32, PT, lane), PT, Ws, PW, acc, wn*32, lane);
#pragma unroll
        for (int mt=0;mt<2;mt++)
#pragma unroll
        for (int nt=0;nt<4;nt++)
#pragma unroll
        for (int e=0;e<4;e++){
            int row = wm*32 + mt*16 + g + ((e&2)?8:0);
            int col = wn*32 + nt*8 + 2*tg + (e&1);
            float h = hreg[mt][nt][e];
            float s = 1.f/(1.f+expf(-h));
            Ab[row*PT+col] = f2tf32(acc[mt][nt][e] * s * (1.f + h*(1.f - s)));
        }
    }
    __syncthreads();

    {   // g0 = K^T @ dh -> gmem
        float acc[4][4][4] = {};
        wtileS<4,4,8,1,0>(Ks, PT, Ab, PT, acc, wm*64, wn*32, lane);
        float* G = d_g0 + (size_t)chunk*DHq*DHq;
#pragma unroll
        for (int mt=0;mt<4;mt++)
#pragma unroll
        for (int nt=0;nt<4;nt++){
            int row = wm*64 + mt*16 + g;
            int col = wn*32 + nt*8 + 2*tg;
            *(float2*)&G[row*DHq + col]     = make_float2(acc[mt][nt][0], acc[mt][nt][1]);
            *(float2*)&G[(row+8)*DHq + col] = make_float2(acc[mt][nt][2], acc[mt][nt][3]);
        }
    }
}

// ---------------- K7: double linear-recurrence scan over N ----------------
__global__ void __launch_bounds__(256) scan_kernel(const float* __restrict__ w0,
                                                   const float* __restrict__ w1)
{
    __shared__ float ams[Nq], dcs[Nq];
    int gid = blockIdx.x*256 + threadIdx.x;     // BH * 16384 threads
    int bh = gid >> 14;
    int e  = gid & 16383;
    if (threadIdx.x < Nq){
        ams[threadIdx.x] = d_am[(size_t)bh*Nq + threadIdx.x];
        dcs[threadIdx.x] = d_dc[(size_t)bh*Nq + threadIdx.x];
    }
    __syncthreads();
    float m0=0.f,u0=0.f,m1=0.f,u1=0.f;
    float wa = w0[e], wb = w1[e];
    size_t base = ((size_t)bh*Nq)*16384 + e;
    for (int n=0;n<Nq;n++){
        float a = ams[n], d = 1.f - dcs[n];
        size_t off = base + (size_t)n*16384;
        m0 = a*m0 - d_g0[off];  u0 = d*u0 + m0;  d_w0t[off] = wa + u0;
        m1 = a*m1 - d_g1[off];  u1 = d*u1 + m1;  d_w1t[off] = wb + u1;
    }
}

// ---------------- K8: per-chunk retrieve MLP + RMSNorm + gate ----------------
__global__ void __launch_bounds__(256) retrieve_kernel(const float* __restrict__ gamma)
{
    extern __shared__ uint32_t smr[];
    uint32_t* Qs = smr;            // q (tf32), later o (fp32)
    uint32_t* Ab = Qs + 64*PT;     // a (tf32)
    uint32_t* Ws = Ab + 64*PT;     // 128*PW
    int tid = threadIdx.x, lane = tid&31, wid = tid>>5;
    int wm = wid>>2, wn = wid&3;
    int g = lane>>2, tg = lane&3;
    int chunk = blockIdx.x;
    int bh = chunk >> 6, n = chunk & 63;
    int b = bh >> 2, h = bh & 3;

    const float4* qg = (const float4*)(d_quer + ((size_t)bh*Lq + n*Cq)*DHq);
#pragma unroll
    for (int u=tid; u<2048; u+=256){
        int r = u>>5, c = (u&31)*4;
        float4 a = qg[u];
        *(uint4*)&Qs[r*PT+c] = make_uint4(f2tf32(a.x),f2tf32(a.y),f2tf32(a.z),f2tf32(a.w));
    }
    const float4* w0c = (const float4*)(d_w0t + (size_t)chunk*DHq*DHq);
#pragma unroll
    for (int u=tid; u<4096; u+=256){
        int r = u>>5, c = (u&31)*4;
        float4 a = w0c[u];
        *(uint4*)&Ws[r*PW+c] = make_uint4(f2tf32(a.x),f2tf32(a.y),f2tf32(a.z),f2tf32(a.w));
    }
    __syncthreads();

    {   // a = silu(q @ w0_t)
        float acc[2][4][4] = {};
        wtileLA<2,4,16,0>(ldsmBase(Qs, wm*32, PT, lane), PT, Ws, PW, acc, wn*32, lane);
#pragma unroll
        for (int mt=0;mt<2;mt++)
#pragma unroll
        for (int nt=0;nt<4;nt++)
#pragma unroll
        for (int e=0;e<4;e++){
            int row = wm*32 + mt*16 + g + ((e&2)?8:0);
            int col = wn*32 + nt*8 + 2*tg + (e&1);
            float hh = acc[mt][nt][e];
            Ab[row*PT+col] = f2tf32(hh/(1.f+expf(-hh)));
        }
    }
    __syncthreads();
    const float4* w1c = (const float4*)(d_w1t + (size_t)chunk*DHq*DHq);
#pragma unroll
    for (int u=tid; u<4096; u+=256){
        int r = u>>5, c = (u&31)*4;
        float4 a = w1c[u];
        *(uint4*)&Ws[r*PW+c] = make_uint4(f2tf32(a.x),f2tf32(a.y),f2tf32(a.z),f2tf32(a.w));
    }
    __syncthreads();

    {   // o = a @ w1_t into Qs (fp32 bits)
        float acc[2][4][4] = {};
        wtileLA<2,4,16,0>(ldsmBase(Ab, wm*32, PT, lane), PT, Ws, PW, acc, wn*32, lane);
        __syncthreads();  // all q-reads done before overwrite
#pragma unroll
        for (int mt=0;mt<2;mt++)
#pragma unroll
        for (int nt=0;nt<4;nt++)
#pragma unroll
        for (int e=0;e<4;e++){
            int row = wm*32 + mt*16 + g + ((e&2)?8:0);
            int col = wn*32 + nt*8 + 2*tg + (e&1);
            Qs[row*PT+col] = __float_as_uint(acc[mt][nt][e]);
        }
    }
    __syncthreads();

    const float* Of = (const float*)Qs;
    int w = tid >> 5;
#pragma unroll
    for (int rr=0; rr<8; rr++){
        int row = w*8 + rr;
        float v0 = Of[row*PT + lane];
        float v1 = Of[row*PT + lane + 32];
        float v2 = Of[row*PT + lane + 64];
        float v3 = Of[row*PT + lane + 96];
        float ss = v0*v0 + v1*v1 + v2*v2 + v3*v3;
#pragma unroll
        for (int off=16;off;off>>=1) ss += __shfl_xor_sync(0xffffffffu, ss, off);
        float sc = rsqrtf(ss*(1.f/DHq) + EPSq);
        int t = n*Cq + row;
        float gt = d_gatev[((size_t)b*Lq + t)*Hq + h];
        float* dst = d_comb + ((size_t)b*Lq + t)*DIMq + h*DHq;
        dst[lane     ] = v0*sc*(gamma[h*DHq + lane     ] + 1.f)*gt;
        dst[lane + 32] = v1*sc*(gamma[h*DHq + lane + 32] + 1.f)*gt;
        dst[lane + 64] = v2*sc*(gamma[h*DHq + lane + 64] + 1.f)*gt;
        dst[lane + 96] = v3*sc*(gamma[h*DHq + lane + 96] + 1.f)*gt;
    }
}

// ---------------- K9: empty-embed fill for first C-1 rows ----------------
__global__ void empty_fill_kernel(const float* __restrict__ emb, float* __restrict__ out)
{
    int gid = blockIdx.x*blockDim.x + threadIdx.x;
    int total = Bq*(Cq-1)*DIMq;
    if (gid >= total) return;
    int d = gid & (DIMq-1);
    int row = gid / DIMq;          // b*(C-1)+t
    int b = row / (Cq-1), t = row % (Cq-1);
    out[((size_t)b*Lq + t)*DIMq + d] = emb[d];
}

// ---------------- launch ----------------
extern "C" void kernel_launch(void* const* d_in, const int* in_sizes, int n_in,
                              void* d_out, int out_size)
{
    const float* seq      = (const float*)d_in[0];
    const float* ss       = (const float*)d_in[1];
    const float* rs       = (const float*)d_in[2];
    const float* w_q      = (const float*)d_in[3];
    const float* w_kv     = (const float*)d_in[4];
    const float* w_ada    = (const float*)d_in[5];
    const float* w_mom    = (const float*)d_in[6];
    const float* w_dec    = (const float*)d_in[7];
    const float* w0       = (const float*)d_in[8];
    const float* w1       = (const float*)d_in[9];
    const float* gamma    = (const float*)d_in[10];
    const float* w_gate   = (const float*)d_in[11];
    const float* w_comb   = (const float*)d_in[12];
    const float* emb      = (const float*)d_in[13];
    float* out = (float*)d_out;

    float *p_snorm, *p_rnorm, *p_keys, *p_vals, *p_quer, *p_comb;
    cudaGetSymbolAddress((void**)&p_snorm, d_s_norm);
    cudaGetSymbolAddress((void**)&p_rnorm, d_r_norm);
    cudaGetSymbolAddress((void**)&p_keys,  d_keys);
    cudaGetSymbolAddress((void**)&p_vals,  d_vals);
    cudaGetSymbolAddress((void**)&p_quer,  d_quer);
    cudaGetSymbolAddress((void**)&p_comb,  d_comb);

    const int SMEM_GEMM = (2*128*GAP + 2*32*GBP) * 4;      // 55296 B
    const int SMEM_G = (3*64*PT + 128*PW) * 4 + 256;       // 171264 B
    const int SMEM_R = (2*64*PT + 128*PW) * 4;             // 137216 B
    cudaFuncSetAttribute(gemm_tc<0>, cudaFuncAttributeMaxDynamicSharedMemorySize, SMEM_GEMM);
    cudaFuncSetAttribute(gemm_tc<1>, cudaFuncAttributeMaxDynamicSharedMemorySize, SMEM_GEMM);
    cudaFuncSetAttribute(gemm_tc<2>, cudaFuncAttributeMaxDynamicSharedMemorySize, SMEM_GEMM);
    cudaFuncSetAttribute(chunk_grad_kernel, cudaFuncAttributeMaxDynamicSharedMemorySize, SMEM_G);
    cudaFuncSetAttribute(retrieve_kernel,   cudaFuncAttributeMaxDynamicSharedMemorySize, SMEM_R);

    // 1. rmsnorms + fused lr/gate projections
    norm_kernel<<<Bq*Lq, 128>>>(seq, ss, rs, w_ada, w_gate);
    // 2. chunk means
    chunk_mean_kernel<<<Bq*Nq, 512>>>();
    // 3. ada_mom / decay
    momdec_kernel<<<(Bq*Nq*32 + 255)/256, 256>>>(w_mom, w_dec);
    // 4. kv projection (keys/vals head-major)
    gemm_tc<0><<<dim3((2*Hq*DHq)/64, (Bq*Lq)/128), 256, SMEM_GEMM>>>(p_snorm, w_kv, p_keys, p_vals, 2*Hq*DHq, DIMq);
    // 5. query projection (reads r_norm shifted)
    gemm_tc<1><<<dim3((Hq*DHq)/64, (Bq*Lq)/128), 256, SMEM_GEMM>>>(p_rnorm, w_q, p_quer, nullptr, Hq*DHq, DIMq);
    // 6. per-chunk gradients
    chunk_grad_kernel<<<NCHUNK, 256, SMEM_G>>>(w0, w1);
    // 7. momentum + decay scans -> per-chunk weights
    scan_kernel<<<(BHq*16384)/256, 256>>>(w0, w1);
    // 8. retrieve MLP + multihead RMSNorm + gate
    retrieve_kernel<<<NCHUNK, 256, SMEM_R>>>(gamma);
    // 9. head combine (writes rows C-1..L-1 of output)
    gemm_tc<2><<<dim3(DIMq/64, (Bq*Lq)/128), 256, SMEM_GEMM>>>(p_comb, w_comb, out, nullptr, DIMq, DIMq);
    // 10. empty rows 0..C-2
    empty_fill_kernel<<<(Bq*(Cq-1)*DIMq + 255)/256, 256>>>(emb, out);
}

// round 4
// speedup vs baseline: 2.9103x; 1.0640x over previous
#include <cuda_runtime.h>
#include <cuda_bf16.h>
#include <math.h>
#include <stdint.h>

// ---------------- problem constants ----------------
#define Bq   2
#define Lq   4096
#define DIMq 512
#define Hq   4
#define DHq  128
#define Cq   64
#define Nq   64          // L / C
#define BHq  8           // B * H
#define NCHUNK 512       // BH * N
#define MAXLR 0.01f
#define EPSq  1e-6f

// ---------------- scratch (device globals; allocation-free) ----------------
__device__ float d_s_norm[Bq*Lq*DIMq];
__device__ float d_r_norm[Bq*Lq*DIMq];
__device__ float d_keys  [BHq*Lq*DHq];
__device__ float d_vals  [BHq*Lq*DHq];
__device__ float d_quer  [BHq*Lq*DHq];
__device__ float d_lr    [BHq*Lq];
__device__ float d_seqmean[Bq*Nq*DIMq];
__device__ float d_am    [BHq*Nq];
__device__ float d_dc    [BHq*Nq];
__device__ float d_g0    [NCHUNK*DHq*DHq];   // TRANSPOSED layout [d2][d1]
__device__ float d_g1    [NCHUNK*DHq*DHq];   // TRANSPOSED layout
__device__ float d_w0t   [NCHUNK*DHq*DHq];   // TRANSPOSED layout [n][k]
__device__ float d_w1t   [NCHUNK*DHq*DHq];   // TRANSPOSED layout
__device__ float d_comb  [Bq*Lq*DIMq];
__device__ float d_gatev [Bq*Lq*Hq];
// pretransposed weights (fp32)
__device__ float d_wkvT[2*Hq*DHq*DIMq];      // [1024][512]
__device__ float d_wqT [Hq*DHq*DIMq];        // [512][512]
__device__ float d_wcT [DIMq*Hq*DHq];        // [512][512]
__device__ float d_w0T [DHq*DHq];
__device__ float d_w1T [DHq*DHq];

__device__ __forceinline__ float sigm(float x){ return 1.f/(1.f+expf(-x)); }

// ---------------- tf32 mma primitives ----------------
__device__ __forceinline__ uint32_t f2tf32(float x){
    uint32_t r; asm("cvt.rna.tf32.f32 %0, %1;" : "=r"(r) : "f"(x)); return r;
}
__device__ __forceinline__ uint32_t ldtf(const float* p){ return f2tf32(*p); }
__device__ __forceinline__ uint32_t ldtf(const uint32_t* p){ return *p; }

__device__ __forceinline__ void mma8(float (&c)[4],
                                     uint32_t a0,uint32_t a1,uint32_t a2,uint32_t a3,
                                     uint32_t b0,uint32_t b1){
    asm volatile("mma.sync.aligned.m16n8k8.row.col.f32.tf32.tf32.f32 "
        "{%0,%1,%2,%3},{%4,%5,%6,%7},{%8,%9},{%0,%1,%2,%3};"
        : "+f"(c[0]),"+f"(c[1]),"+f"(c[2]),"+f"(c[3])
        : "r"(a0),"r"(a1),"r"(a2),"r"(a3),"r"(b0),"r"(b1));
}

__device__ __forceinline__ void ldsm4(uint32_t* r, uint32_t addr){
    asm volatile("ldmatrix.sync.aligned.m8n8.x4.shared.b16 {%0,%1,%2,%3}, [%4];"
        : "=r"(r[0]),"=r"(r[1]),"=r"(r[2]),"=r"(r[3]) : "r"(addr));
}

// per-warp ldmatrix base address (rows = rbase + (lane&15), k-half by lane>>4)
__device__ __forceinline__ uint32_t ldsmBase(const uint32_t* arr, int rbase, int ap, int lane){
    return (uint32_t)__cvta_generic_to_shared(arr)
         + (uint32_t)(((rbase + (lane&15))*ap + ((lane>>4)<<2))*4);
}

// both-side ldmatrix warp tile. aB rows = M, bB rows = N (n-major B).
template<int MT,int NT,int KS>
__device__ __forceinline__ void wtileLL(uint32_t aB,int ap,uint32_t bB,int bp,
                                        float (&acc)[MT][NT][4])
{
#pragma unroll
    for (int ks=0;ks<KS;ks++){
        int k0 = ks*8;
        uint32_t af[MT][4];
#pragma unroll
        for (int mt=0;mt<MT;mt++)
            ldsm4(af[mt], aB + (uint32_t)((mt*16*ap + k0)*4));
        uint32_t bq[NT/2][4];
#pragma unroll
        for (int nt2=0;nt2<NT/2;nt2++)
            ldsm4(bq[nt2], bB + (uint32_t)((nt2*16*bp + k0)*4));
#pragma unroll
        for (int mt=0;mt<MT;mt++)
#pragma unroll
            for (int nt=0;nt<NT;nt++)
                mma8(acc[mt][nt], af[mt][0],af[mt][1],af[mt][2],af[mt][3],
                     bq[nt>>1][nt&1], bq[nt>>1][2+(nt&1)]);
    }
}

// A ldmatrix, B scalar (k-major: B(k,n)=B[k*bp+n])
template<int MT,int NT,int KS>
__device__ __forceinline__ void wtileLS(uint32_t aB,int ap,const uint32_t* B,int bp,
                                        float (&acc)[MT][NT][4], int cbase, int lane)
{
    int g = lane>>2, tg = lane&3;
#pragma unroll
    for (int ks=0;ks<KS;ks++){
        int k0 = ks*8;
        uint32_t af[MT][4];
#pragma unroll
        for (int mt=0;mt<MT;mt++)
            ldsm4(af[mt], aB + (uint32_t)((mt*16*ap + k0)*4));
        uint32_t bf[NT][2];
#pragma unroll
        for (int nt=0;nt<NT;nt++){
            int n = cbase + nt*8 + g;
            bf[nt][0] = B[(k0+tg)*bp + n];
            bf[nt][1] = B[(k0+tg+4)*bp + n];
        }
#pragma unroll
        for (int mt=0;mt<MT;mt++)
#pragma unroll
            for (int nt=0;nt<NT;nt++)
                mma8(acc[mt][nt], af[mt][0],af[mt][1],af[mt][2],af[mt][3],
                     bf[nt][0],bf[nt][1]);
    }
}

// fully scalar warp tile, A transposed in smem (A(row,k)=A[k*ap+row])
template<int MT,int NT,int KS,class TA,class TB>
__device__ __forceinline__ void wtileS(const TA* A,int ap,const TB* B,int bp,
                                       float (&acc)[MT][NT][4], int rbase,int cbase,int lane)
{
    int g = lane>>2, tg = lane&3;
#pragma unroll
    for (int ks=0;ks<KS;ks++){
        int k0 = ks*8 + tg;
        uint32_t af[MT][4];
#pragma unroll
        for (int mt=0;mt<MT;mt++){
            int r0 = rbase + mt*16 + g;
            af[mt][0]=ldtf(&A[k0*ap + r0]);
            af[mt][1]=ldtf(&A[k0*ap + r0+8]);
            af[mt][2]=ldtf(&A[(k0+4)*ap + r0]);
            af[mt][3]=ldtf(&A[(k0+4)*ap + r0+8]);
        }
        uint32_t bf[NT][2];
#pragma unroll
        for (int nt=0;nt<NT;nt++){
            int n = cbase + nt*8 + g;
            bf[nt][0]=ldtf(&B[k0*bp + n]);
            bf[nt][1]=ldtf(&B[(k0+4)*bp + n]);
        }
#pragma unroll
        for (int mt=0;mt<MT;mt++)
#pragma unroll
            for (int nt=0;nt<NT;nt++)
                mma8(acc[mt][nt], af[mt][0],af[mt][1],af[mt][2],af[mt][3],
                     bf[nt][0],bf[nt][1]);
    }
}

// ---------------- transpose kernel (fp32) ----------------
__global__ void __launch_bounds__(256) transpose_kernel(const float* __restrict__ in,
                                                        float* __restrict__ out,
                                                        int R, int Cc)
{
    __shared__ float t[32][33];
    int bx = blockIdx.x*32, by = blockIdx.y*32;
#pragma unroll
    for (int i=0;i<4;i++)
        t[threadIdx.y + 8*i][threadIdx.x] = in[(size_t)(by + threadIdx.y + 8*i)*Cc + bx + threadIdx.x];
    __syncthreads();
#pragma unroll
    for (int i=0;i<4;i++)
        out[(size_t)(bx + threadIdx.y + 8*i)*R + by + threadIdx.x] = t[threadIdx.x][threadIdx.y + 8*i];
}

// ---------------- K1: per-token rmsnorm + fused lr/gate projections ----------------
__global__ void __launch_bounds__(128) norm_kernel(const float* __restrict__ seq,
                                                   const float* __restrict__ ss,
                                                   const float* __restrict__ rs,
                                                   const float* __restrict__ w_ada,
                                                   const float* __restrict__ w_gate)
{
    int token = blockIdx.x;              // b*L + t
    int tid = threadIdx.x;
    int lane = tid & 31, w = tid >> 5;
    const float* x = seq + (size_t)token*DIMq;
    float v[4]; float acc = 0.f;
#pragma unroll
    for (int i=0;i<4;i++){ v[i] = x[tid + 128*i]; acc += v[i]*v[i]; }
#pragma unroll
    for (int off=16;off;off>>=1) acc += __shfl_xor_sync(0xffffffffu, acc, off);
    __shared__ float red[4];
    __shared__ float red8[4][8];
    if (lane==0) red[w] = acc;
    __syncthreads();
    float tot = red[0]+red[1]+red[2]+red[3];
    float rms = rsqrtf(tot*(1.f/DIMq) + EPSq);
    float p[8] = {0,0,0,0,0,0,0,0};
#pragma unroll
    for (int i=0;i<4;i++){
        int d = tid + 128*i;
        float y = v[i]*rms;
        float ysv = y*ss[d], yrv = y*rs[d];
        d_s_norm[(size_t)token*DIMq + d] = ysv;
        d_r_norm[(size_t)token*DIMq + d] = yrv;
#pragma unroll
        for (int h=0;h<4;h++){
            p[h]   += ysv*w_ada [d*4+h];
            p[4+h] += yrv*w_gate[d*4+h];
        }
    }
#pragma unroll
    for (int h=0;h<8;h++)
#pragma unroll
        for (int off=16;off;off>>=1) p[h] += __shfl_xor_sync(0xffffffffu, p[h], off);
    if (lane==0)
#pragma unroll
        for (int h=0;h<8;h++) red8[w][h] = p[h];
    __syncthreads();
    if (tid < 8){
        float s = red8[0][tid]+red8[1][tid]+red8[2][tid]+red8[3][tid];
        int b = token >> 12, t = token & (Lq-1);
        if (tid < 4)
            d_lr[((size_t)(b*Hq+tid))*Lq + t] = sigm(s)*MAXLR;
        else if (t >= Cq-1)
            d_gatev[((size_t)b*Lq + (t-(Cq-1)))*Hq + (tid-4)] = sigm(s);
    }
}

// ---------------- chunk means of s ----------------
__global__ void __launch_bounds__(512) chunk_mean_kernel()
{
    int bn = blockIdx.x;            // b*N + n
    int d = threadIdx.x;
    int b = bn / Nq, n = bn % Nq;
    const float* base = d_s_norm + ((size_t)b*Lq + n*Cq)*DIMq + d;
    float acc = 0.f;
#pragma unroll 8
    for (int c=0;c<Cq;c++) acc += base[(size_t)c*DIMq];
    d_seqmean[(size_t)bn*DIMq + d] = acc*(1.f/Cq);
}

// ---------------- ada_mom / decay from seq_mean ----------------
__global__ void momdec_kernel(const float* __restrict__ wm, const float* __restrict__ wd)
{
    int warp = (blockIdx.x*blockDim.x + threadIdx.x) >> 5;
    int lane = threadIdx.x & 31;
    if (warp >= Bq*Nq) return;
    const float* x = d_seqmean + (size_t)warp*DIMq;
    float a[4]={0,0,0,0}, b4[4]={0,0,0,0};
    for (int d=lane; d<DIMq; d+=32){
        float xv = x[d];
#pragma unroll
        for (int h=0;h<4;h++){ a[h]+=xv*wm[d*4+h]; b4[h]+=xv*wd[d*4+h]; }
    }
#pragma unroll
    for (int off=16;off;off>>=1)
#pragma unroll
        for (int h=0;h<4;h++){
            a[h]  += __shfl_down_sync(0xffffffffu,a[h],off);
            b4[h] += __shfl_down_sync(0xffffffffu,b4[h],off);
        }
    if (lane==0){
        int b = warp / Nq, n = warp % Nq;
#pragma unroll
        for (int h=0;h<4;h++){
            d_am[(size_t)(b*Hq+h)*Nq + n] = sigm(a[h]);
            d_dc[(size_t)(b*Hq+h)*Nq + n] = sigm(b4[h]);
        }
    }
}

// ---------------- big GEMM, tf32 TC, both-side ldmatrix, double-buffered ----------------
// WT: pretransposed weights [N][K]
// MODE 0: keys/vals head-major; MODE 1: A shifted from r_norm, out queries; MODE 2: out shifted
#define GAP 36
#define GBP 36
template<int MODE>
__global__ void __launch_bounds__(256) gemm_tc(const float* __restrict__ A,
                                               const float* __restrict__ WT,
                                               float* __restrict__ out0,
                                               float* __restrict__ out1,
                                               int K)
{
    extern __shared__ uint32_t sh[];
    uint32_t* Asb[2] = { sh, sh + 128*GAP };
    uint32_t* Bsb[2] = { sh + 2*128*GAP, sh + 2*128*GAP + 64*GBP };
    int tid = threadIdx.x, lane = tid & 31, wid = tid >> 5;
    int wm = wid >> 1, wn = wid & 1;       // 4 x 2 warps, 32x32 tiles
    int m0 = blockIdx.y*128, n0 = blockIdx.x*64;
    float acc[2][4][4] = {};
    int ar = tid>>3, ac4 = tid&7;          // A loads: rows ar+32i
    int bn = tid>>3, bk4 = tid&7;          // B loads: n rows bn+32i
    float4 ra[4], rb[2];

    const int NK = K/32;
#pragma unroll 1
    for (int kt=-1; kt<NK; kt++){
        if (kt+1 < NK){                    // prefetch tile kt+1
            int k0 = (kt+1)*32;
#pragma unroll
            for (int i=0;i<4;i++){
                int gr = m0 + ar + 32*i;
                if (MODE==1){
                    int t = gr & (Lq-1);
                    ra[i] = (t <= Lq-Cq) ? *(const float4*)&A[(size_t)(gr+Cq-1)*K + k0 + ac4*4]
                                         : make_float4(0.f,0.f,0.f,0.f);
                } else ra[i] = *(const float4*)&A[(size_t)gr*K + k0 + ac4*4];
            }
#pragma unroll
            for (int i=0;i<2;i++)
                rb[i] = *(const float4*)&WT[(size_t)(n0 + bn + 32*i)*K + k0 + bk4*4];
        }
        if (kt >= 0){                      // compute on buffer kt&1
            int b = kt&1;
            wtileLL<2,4,4>(ldsmBase(Asb[b], wm*32, GAP, lane), GAP,
                           ldsmBase(Bsb[b], wn*32, GBP, lane), GBP, acc);
            __syncthreads();
        }
        if (kt+1 < NK){                    // store prefetched tile
            int b = (kt+1)&1;
#pragma unroll
            for (int i=0;i<4;i++)
                *(uint4*)&Asb[b][(ar+32*i)*GAP + ac4*4] =
                    make_uint4(f2tf32(ra[i].x),f2tf32(ra[i].y),f2tf32(ra[i].z),f2tf32(ra[i].w));
#pragma unroll
            for (int i=0;i<2;i++)
                *(uint4*)&Bsb[b][(bn+32*i)*GBP + bk4*4] =
                    make_uint4(f2tf32(rb[i].x),f2tf32(rb[i].y),f2tf32(rb[i].z),f2tf32(rb[i].w));
            __syncthreads();
        }
    }

    int g = lane>>2, tg = lane&3;
#pragma unroll
    for (int mt=0;mt<2;mt++)
#pragma unroll
    for (int nt=0;nt<4;nt++)
#pragma unroll
    for (int e=0;e<4;e++){
        int row = m0 + wm*32 + mt*16 + g + ((e&2)?8:0);
        int col = n0 + wn*32 + nt*8 + 2*tg + (e&1);
        float v = acc[mt][nt][e];
        int b = row >> 12, t = row & (Lq-1);
        if (MODE==0){
            if (col < Hq*DHq){
                int h = col>>7, d = col&127;
                out0[((size_t)(b*Hq+h)*Lq + t)*DHq + d] = v;
            } else {
                int c2 = col - Hq*DHq; int h = c2>>7, d = c2&127;
                out1[((size_t)(b*Hq+h)*Lq + t)*DHq + d] = v;
            }
        } else if (MODE==1){
            int h = col>>7, d = col&127;
            out0[((size_t)(b*Hq+h)*Lq + t)*DHq + d] = v;
        } else {
            if (t <= Lq - Cq)
                out0[((size_t)b*Lq + t + Cq - 1)*DIMq + col] = v;
        }
    }
}

// ---------------- per-chunk kernels ----------------
#define PT 132   // pitch, ldsm-conflict-free (132*4/16 = 33, odd)

// ---------------- chunk gradient ----------------
__global__ void __launch_bounds__(256) chunk_grad_kernel(const float* __restrict__ w1nat_unused)
{
    extern __shared__ uint32_t smu[];
    uint32_t* Ks = smu;            // 64*PT  keys (tf32)
    uint32_t* Ab = Ks + 64*PT;     // a=silu(h) (tf32), later dh
    uint32_t* Db = Ab + 64*PT;     // v (raw fp32), later dpred (tf32)
    uint32_t* Ws = Db + 64*PT;     // 128*PT weights (w0T, then w1T)
    float* Lr = (float*)(Ws + 128*PT); // 64
    int tid = threadIdx.x, lane = tid&31, wid = tid>>5;
    int wm = wid>>2, wn = wid&3;   // 2 x 4 warps
    int g = lane>>2, tg = lane&3;
    int chunk = blockIdx.x;
    int bh = chunk >> 6, t0 = (chunk & 63) << 6;

    const float4* kg = (const float4*)(d_keys + ((size_t)bh*Lq + t0)*DHq);
    const float4* vg = (const float4*)(d_vals + ((size_t)bh*Lq + t0)*DHq);
#pragma unroll
    for (int u=tid; u<2048; u+=256){
        int r = u>>5, c = (u&31)*4;
        float4 a = kg[u], b = vg[u];
        *(uint4*)&Ks[r*PT+c] = make_uint4(f2tf32(a.x),f2tf32(a.y),f2tf32(a.z),f2tf32(a.w));
        *(uint4*)&Db[r*PT+c] = make_uint4(__float_as_uint(b.x),__float_as_uint(b.y),
                                          __float_as_uint(b.z),__float_as_uint(b.w));
    }
    if (tid < 64) Lr[tid] = d_lr[(size_t)bh*Lq + t0 + tid];
    const float4* wT4 = (const float4*)d_w0T;
#pragma unroll
    for (int u=tid; u<4096; u+=256){
        int r = u>>5, c = (u&31)*4;
        float4 a = wT4[u];
        *(uint4*)&Ws[r*PT+c] = make_uint4(f2tf32(a.x),f2tf32(a.y),f2tf32(a.z),f2tf32(a.w));
    }
    __syncthreads();

    // h = K @ w0 (B n-major = w0T); keep h in regs; a = silu(h) -> Ab
    float hreg[2][4][4] = {};
    wtileLL<2,4,16>(ldsmBase(Ks, wm*32, PT, lane), PT,
                    ldsmBase(Ws, wn*32, PT, lane), PT, hreg);
#pragma unroll
    for (int mt=0;mt<2;mt++)
#pragma unroll
    for (int nt=0;nt<4;nt++)
#pragma unroll
    for (int e=0;e<4;e++){
        int row = wm*32 + mt*16 + g + ((e&2)?8:0);
        int col = wn*32 + nt*8 + 2*tg + (e&1);
        float h = hreg[mt][nt][e];
        Ab[row*PT+col] = f2tf32(h/(1.f+expf(-h)));
    }
    __syncthreads();
    const float4* w1T4 = (const float4*)d_w1T;
#pragma unroll
    for (int u=tid; u<4096; u+=256){
        int r = u>>5, c = (u&31)*4;
        float4 a = w1T4[u];
        *(uint4*)&Ws[r*PT+c] = make_uint4(f2tf32(a.x),f2tf32(a.y),f2tf32(a.z),f2tf32(a.w));
    }
    __syncthreads();

    {   // pred = a @ w1 (B n-major = w1T) ; dpred = lr*2/DH*(pred-v) -> Db (tf32)
        float acc[2][4][4] = {};
        wtileLL<2,4,16>(ldsmBase(Ab, wm*32, PT, lane), PT,
                        ldsmBase(Ws, wn*32, PT, lane), PT, acc);
#pragma unroll
        for (int mt=0;mt<2;mt++)
#pragma unroll
        for (int nt=0;nt<4;nt++)
#pragma unroll
        for (int e=0;e<4;e++){
            int row = wm*32 + mt*16 + g + ((e&2)?8:0);
            int col = wn*32 + nt*8 + 2*tg + (e&1);
            float v = __uint_as_float(Db[row*PT+col]);
            Db[row*PT+col] = f2tf32(Lr[row]*(2.f/DHq)*(acc[mt][nt][e] - v));
        }
    }
    __syncthreads();

    {   // g1^T = dpred^T @ a -> gmem (transposed layout)
        float acc[4][4][4] = {};
        wtileS<4,4,8>(Db, PT, Ab, PT, acc, wm*64, wn*32, lane);
        float* G = d_g1 + (size_t)chunk*DHq*DHq;
#pragma unroll
        for (int mt=0;mt<4;mt++)
#pragma unroll
        for (int nt=0;nt<4;nt++){
            int row = wm*64 + mt*16 + g;
            int col = wn*32 + nt*8 + 2*tg;
            *(float2*)&G[row*DHq + col]     = make_float2(acc[mt][nt][0], acc[mt][nt][1]);
            *(float2*)&G[(row+8)*DHq + col] = make_float2(acc[mt][nt][2], acc[mt][nt][3]);
        }
    }
    __syncthreads();

    {   // da = dpred @ w1^T : B(k,n) = w1[n][k] = w1T[k][n] -> scalar k-major from Ws
        float acc[2][4][4] = {};
        wtileLS<2,4,16>(ldsmBase(Db, wm*32, PT, lane), PT, Ws, PT, acc, wn*32, lane);
#pragma unroll
        for (int mt=0;mt<2;mt++)
#pragma unroll
        for (int nt=0;nt<4;nt++)
#pragma unroll
        for (int e=0;e<4;e++){
            int row = wm*32 + mt*16 + g + ((e&2)?8:0);
            int col = wn*32 + nt*8 + 2*tg + (e&1);
            float h = hreg[mt][nt][e];
            float s = 1.f/(1.f+expf(-h));
            Ab[row*PT+col] = f2tf32(acc[mt][nt][e] * s * (1.f + h*(1.f - s)));
        }
    }
    __syncthreads();

    {   // g0^T = dh^T @ K -> gmem (transposed layout)
        float acc[4][4][4] = {};
        wtileS<4,4,8>(Ab, PT, Ks, PT, acc, wm*64, wn*32, lane);
        float* G = d_g0 + (size_t)chunk*DHq*DHq;
#pragma unroll
        for (int mt=0;mt<4;mt++)
#pragma unroll
        for (int nt=0;nt<4;nt++){
            int row = wm*64 + mt*16 + g;
            int col = wn*32 + nt*8 + 2*tg;
            *(float2*)&G[row*DHq + col]     = make_float2(acc[mt][nt][0], acc[mt][nt][1]);
            *(float2*)&G[(row+8)*DHq + col] = make_float2(acc[mt][nt][2], acc[mt][nt][3]);
        }
    }
}

// ---------------- scan (transposed layout throughout) ----------------
__global__ void __launch_bounds__(256) scan_kernel()
{
    __shared__ float ams[Nq], dcs[Nq];
    int gid = blockIdx.x*256 + threadIdx.x;     // BH * 16384 threads
    int bh = gid >> 14;
    int e  = gid & 16383;
    if (threadIdx.x < Nq){
        ams[threadIdx.x] = d_am[(size_t)bh*Nq + threadIdx.x];
        dcs[threadIdx.x] = d_dc[(size_t)bh*Nq + threadIdx.x];
    }
    __syncthreads();
    float m0=0.f,u0=0.f,m1=0.f,u1=0.f;
    float wa = d_w0T[e], wb = d_w1T[e];
    size_t base = ((size_t)bh*Nq)*16384 + e;
    for (int n=0;n<Nq;n++){
        float a = ams[n], d = 1.f - dcs[n];
        size_t off = base + (size_t)n*16384;
        m0 = a*m0 - d_g0[off];  u0 = d*u0 + m0;  d_w0t[off] = wa + u0;
        m1 = a*m1 - d_g1[off];  u1 = d*u1 + m1;  d_w1t[off] = wb + u1;
    }
}

// ---------------- retrieve MLP + RMSNorm + gate ----------------
__global__ void __launch_bounds__(256) retrieve_kernel(const float* __restrict__ gamma)
{
    extern __shared__ uint32_t smr[];
    uint32_t* Qs = smr;            // q (tf32), later o (fp32)
    uint32_t* Ab = Qs + 64*PT;     // a (tf32)
    uint32_t* Ws = Ab + 64*PT;     // 128*PT (w0tT then w1tT — already transposed)
    int tid = threadIdx.x, lane = tid&31, wid = tid>>5;
    int wm = wid>>2, wn = wid&3;
    int g = lane>>2, tg = lane&3;
    int chunk = blockIdx.x;
    int bh = chunk >> 6, n = chunk & 63;
    int b = bh >> 2, h = bh & 3;

    const float4* qg = (const float4*)(d_quer + ((size_t)bh*Lq + n*Cq)*DHq);
#pragma unroll
    for (int u=tid; u<2048; u+=256){
        int r = u>>5, c = (u&31)*4;
        float4 a = qg[u];
        *(uint4*)&Qs[r*PT+c] = make_uint4(f2tf32(a.x),f2tf32(a.y),f2tf32(a.z),f2tf32(a.w));
    }
    const float4* w0c = (const float4*)(d_w0t + (size_t)chunk*DHq*DHq);
#pragma unroll
    for (int u=tid; u<4096; u+=256){
        int r = u>>5, c = (u&31)*4;
        float4 a = w0c[u];
        *(uint4*)&Ws[r*PT+c] = make_uint4(f2tf32(a.x),f2tf32(a.y),f2tf32(a.z),f2tf32(a.w));
    }
    __syncthreads();

    {   // a = silu(q @ w0_t)  (B n-major = stored transposed w0t)
        float acc[2][4][4] = {};
        wtileLL<2,4,16>(ldsmBase(Qs, wm*32, PT, lane), PT,
                        ldsmBase(Ws, wn*32, PT, lane), PT, acc);
#pragma unroll
        for (int mt=0;mt<2;mt++)
#pragma unroll
        for (int nt=0;nt<4;nt++)
#pragma unroll
        for (int e=0;e<4;e++){
            int row = wm*32 + mt*16 + g + ((e&2)?8:0);
            int col = wn*32 + nt*8 + 2*tg + (e&1);
            float hh = acc[mt][nt][e];
            Ab[row*PT+col] = f2tf32(hh/(1.f+expf(-hh)));
        }
    }
    __syncthreads();
    const float4* w1c = (const float4*)(d_w1t + (size_t)chunk*DHq*DHq);
#pragma unroll
    for (int u=tid; u<4096; u+=256){
        int r = u>>5, c = (u&31)*4;
        float4 a = w1c[u];
        *(uint4*)&Ws[r*PT+c] = make_uint4(f2tf32(a.x),f2tf32(a.y),f2tf32(a.z),f2tf32(a.w));
    }
    __syncthreads();

    {   // o = a @ w1_t into Qs (fp32 bits)
        float acc[2][4][4] = {};
        wtileLL<2,4,16>(ldsmBase(Ab, wm*32, PT, lane), PT,
                        ldsmBase(Ws, wn*32, PT, lane), PT, acc);
        __syncthreads();
#pragma unroll
        for (int mt=0;mt<2;mt++)
#pragma unroll
        for (int nt=0;nt<4;nt++)
#pragma unroll
        for (int e=0;e<4;e++){
            int row = wm*32 + mt*16 + g + ((e&2)?8:0);
            int col = wn*32 + nt*8 + 2*tg + (e&1);
            Qs[row*PT+col] = __float_as_uint(acc[mt][nt][e]);
        }
    }
    __syncthreads();

    const float* Of = (const float*)Qs;
    int w = tid >> 5;
#pragma unroll
    for (int rr=0; rr<8; rr++){
        int row = w*8 + rr;
        float v0 = Of[row*PT + lane];
        float v1 = Of[row*PT + lane + 32];
        float v2 = Of[row*PT + lane + 64];
        float v3 = Of[row*PT + lane + 96];
        float ss = v0*v0 + v1*v1 + v2*v2 + v3*v3;
#pragma unroll
        for (int off=16;off;off>>=1) ss += __shfl_xor_sync(0xffffffffu, ss, off);
        float sc = rsqrtf(ss*(1.f/DHq) + EPSq);
        int t = n*Cq + row;
        float gt = d_gatev[((size_t)b*Lq + t)*Hq + h];
        float* dst = d_comb + ((size_t)b*Lq + t)*DIMq + h*DHq;
        dst[lane     ] = v0*sc*(gamma[h*DHq + lane     ] + 1.f)*gt;
        dst[lane + 32] = v1*sc*(gamma[h*DHq + lane + 32] + 1.f)*gt;
        dst[lane + 64] = v2*sc*(gamma[h*DHq + lane + 64] + 1.f)*gt;
        dst[lane + 96] = v3*sc*(gamma[h*DHq + lane + 96] + 1.f)*gt;
    }
}

// ---------------- empty-embed fill for first C-1 rows ----------------
__global__ void empty_fill_kernel(const float* __restrict__ emb, float* __restrict__ out)
{
    int gid = blockIdx.x*blockDim.x + threadIdx.x;
    int total = Bq*(Cq-1)*DIMq;
    if (gid >= total) return;
    int d = gid & (DIMq-1);
    int row = gid / DIMq;          // b*(C-1)+t
    int b = row / (Cq-1), t = row % (Cq-1);
    out[((size_t)b*Lq + t)*DIMq + d] = emb[d];
}

// ---------------- launch ----------------
extern "C" void kernel_launch(void* const* d_in, const int* in_sizes, int n_in,
                              void* d_out, int out_size)
{
    const float* seq      = (const float*)d_in[0];
    const float* ss       = (const float*)d_in[1];
    const float* rs       = (const float*)d_in[2];
    const float* w_q      = (const float*)d_in[3];
    const float* w_kv     = (const float*)d_in[4];
    const float* w_ada    = (const float*)d_in[5];
    const float* w_mom    = (const float*)d_in[6];
    const float* w_dec    = (const float*)d_in[7];
    const float* w0       = (const float*)d_in[8];
    const float* w1       = (const float*)d_in[9];
    const float* gamma    = (const float*)d_in[10];
    const float* w_gate   = (const float*)d_in[11];
    const float* w_comb   = (const float*)d_in[12];
    const float* emb      = (const float*)d_in[13];
    float* out = (float*)d_out;

    float *p_snorm, *p_rnorm, *p_keys, *p_vals, *p_quer, *p_comb;
    float *p_wkvT, *p_wqT, *p_wcT, *p_w0T, *p_w1T;
    cudaGetSymbolAddress((void**)&p_snorm, d_s_norm);
    cudaGetSymbolAddress((void**)&p_rnorm, d_r_norm);
    cudaGetSymbolAddress((void**)&p_keys,  d_keys);
    cudaGetSymbolAddress((void**)&p_vals,  d_vals);
    cudaGetSymbolAddress((void**)&p_quer,  d_quer);
    cudaGetSymbolAddress((void**)&p_comb,  d_comb);
    cudaGetSymbolAddress((void**)&p_wkvT,  d_wkvT);
    cudaGetSymbolAddress((void**)&p_wqT,   d_wqT);
    cudaGetSymbolAddress((void**)&p_wcT,   d_wcT);
    cudaGetSymbolAddress((void**)&p_w0T,   d_w0T);
    cudaGetSymbolAddress((void**)&p_w1T,   d_w1T);

    const int SMEM_GEMM = (2*128*GAP + 2*64*GBP) * 4;      // 55296 B
    const int SMEM_G = (3*64*PT + 128*PT) * 4 + 256;       // ~169 KB
    const int SMEM_R = (2*64*PT + 128*PT) * 4;             // ~135 KB
    cudaFuncSetAttribute(gemm_tc<0>, cudaFuncAttributeMaxDynamicSharedMemorySize, SMEM_GEMM);
    cudaFuncSetAttribute(gemm_tc<1>, cudaFuncAttributeMaxDynamicSharedMemorySize, SMEM_GEMM);
    cudaFuncSetAttribute(gemm_tc<2>, cudaFuncAttributeMaxDynamicSharedMemorySize, SMEM_GEMM);
    cudaFuncSetAttribute(chunk_grad_kernel, cudaFuncAttributeMaxDynamicSharedMemorySize, SMEM_G);
    cudaFuncSetAttribute(retrieve_kernel,   cudaFuncAttributeMaxDynamicSharedMemorySize, SMEM_R);

    // fork/join streams (capture-safe: fork from legacy stream via events)
    cudaStream_t s1, s2;
    cudaStreamCreateWithFlags(&s1, cudaStreamNonBlocking);
    cudaStreamCreateWithFlags(&s2, cudaStreamNonBlocking);
    cudaEvent_t e0, et, en, eq, em;
    cudaEventCreateWithFlags(&e0, cudaEventDisableTiming);
    cudaEventCreateWithFlags(&et, cudaEventDisableTiming);
    cudaEventCreateWithFlags(&en, cudaEventDisableTiming);
    cudaEventCreateWithFlags(&eq, cudaEventDisableTiming);
    cudaEventCreateWithFlags(&em, cudaEventDisableTiming);

    cudaEventRecord(e0, 0);
    cudaStreamWaitEvent(s1, e0, 0);
    cudaStreamWaitEvent(s2, e0, 0);

    // s1: weight transposes + empty fill (independent of norm)
    transpose_kernel<<<dim3(1024/32, 512/32), dim3(32,8), 0, s1>>>(w_kv,   p_wkvT, DIMq, 2*Hq*DHq);
    transpose_kernel<<<dim3(512/32,  512/32), dim3(32,8), 0, s1>>>(w_q,    p_wqT,  DIMq, Hq*DHq);
    transpose_kernel<<<dim3(512/32,  512/32), dim3(32,8), 0, s1>>>(w_comb, p_wcT,  Hq*DHq, DIMq);
    transpose_kernel<<<dim3(4,4),             dim3(32,8), 0, s1>>>(w0,     p_w0T,  DHq, DHq);
    transpose_kernel<<<dim3(4,4),             dim3(32,8), 0, s1>>>(w1,     p_w1T,  DHq, DHq);
    empty_fill_kernel<<<(Bq*(Cq-1)*DIMq + 255)/256, 256, 0, s1>>>(emb, out);
    cudaEventRecord(et, s1);

    // main: rmsnorms + fused projections
    norm_kernel<<<Bq*Lq, 128>>>(seq, ss, rs, w_ada, w_gate);
    cudaEventRecord(en, 0);

    // s1: chunk means -> momdec (needs norm)
    cudaStreamWaitEvent(s1, en, 0);
    chunk_mean_kernel<<<Bq*Nq, 512, 0, s1>>>();
    momdec_kernel<<<(Bq*Nq*32 + 255)/256, 256, 0, s1>>>(w_mom, w_dec);
    cudaEventRecord(em, s1);

    // s2: query projection (needs norm + wqT)
    cudaStreamWaitEvent(s2, en, 0);
    cudaStreamWaitEvent(s2, et, 0);
    gemm_tc<1><<<dim3((Hq*DHq)/64, (Bq*Lq)/128), 256, SMEM_GEMM, s2>>>(p_rnorm, p_wqT, p_quer, nullptr, DIMq);
    cudaEventRecord(eq, s2);

    // main chain
    cudaStreamWaitEvent(0, et, 0);
    gemm_tc<0><<<dim3((2*Hq*DHq)/64, (Bq*Lq)/128), 256, SMEM_GEMM>>>(p_snorm, p_wkvT, p_keys, p_vals, DIMq);
    chunk_grad_kernel<<<NCHUNK, 256, SMEM_G>>>(nullptr);
    cudaStreamWaitEvent(0, em, 0);
    scan_kernel<<<(BHq*16384)/256, 256>>>();
    cudaStreamWaitEvent(0, eq, 0);
    retrieve_kernel<<<NCHUNK, 256, SMEM_R>>>(gamma);
    gemm_tc<2><<<dim3(DIMq/64, (Bq*Lq)/128), 256, SMEM_GEMM>>>(p_comb, p_wcT, out, nullptr, Hq*DHq);

    // destroy only when not capturing (destroy during capture is illegal; bounded leak otherwise)
    cudaStreamCaptureStatus cap = cudaStreamCaptureStatusNone;
    cudaStreamIsCapturing(0, &cap);
    if (cap == cudaStreamCaptureStatusNone){
        cudaStreamDestroy(s1); cudaStreamDestroy(s2);
        cudaEventDestroy(e0); cudaEventDestroy(et); cudaEventDestroy(en);
        cudaEventDestroy(eq); cudaEventDestroy(em);
    }
}

// round 5
// speedup vs baseline: 3.3813x; 1.1618x over previous
#include <cuda_runtime.h>
#include <cuda_bf16.h>
#include <math.h>
#include <stdint.h>

// ---------------- problem constants ----------------
#define Bq   2
#define Lq   4096
#define DIMq 512
#define Hq   4
#define DHq  128
#define Cq   64
#define Nq   64          // L / C
#define BHq  8           // B * H
#define NCHUNK 512       // BH * N
#define MAXLR 0.01f
#define EPSq  1e-6f

// ---------------- scratch (device globals; allocation-free) ----------------
// NOTE: all buffers marked (tf32) hold fp32 values pre-rounded to tf32.
__device__ float d_s_norm[Bq*Lq*DIMq];       // (tf32)
__device__ float d_r_norm[Bq*Lq*DIMq];       // (tf32)
__device__ float d_keys  [BHq*Lq*DHq];       // (tf32)
__device__ float d_vals  [BHq*Lq*DHq];       // fp32
__device__ float d_quer  [BHq*Lq*DHq];       // (tf32)
__device__ float d_lr    [BHq*Lq];
__device__ float d_seqmean[Bq*Nq*DIMq];
__device__ float d_am    [BHq*Nq];
__device__ float d_dc    [BHq*Nq];
__device__ float d_g0    [NCHUNK*DHq*DHq];   // fp32, TRANSPOSED layout
__device__ float d_g1    [NCHUNK*DHq*DHq];   // fp32, TRANSPOSED layout
__device__ float d_w0t   [NCHUNK*DHq*DHq];   // (tf32), TRANSPOSED layout
__device__ float d_w1t   [NCHUNK*DHq*DHq];   // (tf32), TRANSPOSED layout
__device__ float d_comb  [Bq*Lq*DIMq];       // (tf32)
__device__ float d_gatev [Bq*Lq*Hq];
// pretransposed weights, (tf32)
__device__ float d_wkvT[2*Hq*DHq*DIMq];
__device__ float d_wqT [Hq*DHq*DIMq];
__device__ float d_wcT [DIMq*Hq*DHq];
__device__ float d_w0T [DHq*DHq];
__device__ float d_w1T [DHq*DHq];

__device__ __forceinline__ float sigm(float x){ return 1.f/(1.f+expf(-x)); }

// ---------------- tf32 mma primitives ----------------
__device__ __forceinline__ uint32_t f2tf32(float x){
    uint32_t r; asm("cvt.rna.tf32.f32 %0, %1;" : "=r"(r) : "f"(x)); return r;
}
__device__ __forceinline__ float f2tf32f(float x){ return __uint_as_float(f2tf32(x)); }
__device__ __forceinline__ uint32_t ldtf(const uint32_t* p){ return *p; }

__device__ __forceinline__ void mma8(float (&c)[4],
                                     uint32_t a0,uint32_t a1,uint32_t a2,uint32_t a3,
                                     uint32_t b0,uint32_t b1){
    asm volatile("mma.sync.aligned.m16n8k8.row.col.f32.tf32.tf32.f32 "
        "{%0,%1,%2,%3},{%4,%5,%6,%7},{%8,%9},{%0,%1,%2,%3};"
        : "+f"(c[0]),"+f"(c[1]),"+f"(c[2]),"+f"(c[3])
        : "r"(a0),"r"(a1),"r"(a2),"r"(a3),"r"(b0),"r"(b1));
}

__device__ __forceinline__ void ldsm4(uint32_t* r, uint32_t addr){
    asm volatile("ldmatrix.sync.aligned.m8n8.x4.shared.b16 {%0,%1,%2,%3}, [%4];"
        : "=r"(r[0]),"=r"(r[1]),"=r"(r[2]),"=r"(r[3]) : "r"(addr));
}

__device__ __forceinline__ uint32_t ldsmBase(uint32_t shAddr, int rbase, int ap, int lane){
    return shAddr + (uint32_t)(((rbase + (lane&15))*ap + ((lane>>4)<<2))*4);
}

// ---------------- cp.async helpers ----------------
__device__ __forceinline__ void cpa16(uint32_t dst, const float* src){
    asm volatile("cp.async.ca.shared.global [%0],[%1],16;"::"r"(dst),"l"(src));
}
__device__ __forceinline__ void cpa16z(uint32_t dst, const float* src, bool p){
    int sz = p ? 16 : 0;
    asm volatile("cp.async.ca.shared.global [%0],[%1],16,%2;"::"r"(dst),"l"(src),"r"(sz));
}
__device__ __forceinline__ void cpcommit(){ asm volatile("cp.async.commit_group;"); }
template<int N> __device__ __forceinline__ void cpwait(){ asm volatile("cp.async.wait_group %0;"::"n"(N)); }

// both-side ldmatrix warp tile
template<int MT,int NT,int KS>
__device__ __forceinline__ void wtileLL(uint32_t aB,int ap,uint32_t bB,int bp,
                                        float (&acc)[MT][NT][4])
{
#pragma unroll
    for (int ks=0;ks<KS;ks++){
        int k0 = ks*8;
        uint32_t af[MT][4];
#pragma unroll
        for (int mt=0;mt<MT;mt++)
            ldsm4(af[mt], aB + (uint32_t)((mt*16*ap + k0)*4));
        uint32_t bq[NT/2][4];
#pragma unroll
        for (int nt2=0;nt2<NT/2;nt2++)
            ldsm4(bq[nt2], bB + (uint32_t)((nt2*16*bp + k0)*4));
#pragma unroll
        for (int mt=0;mt<MT;mt++)
#pragma unroll
            for (int nt=0;nt<NT;nt++)
                mma8(acc[mt][nt], af[mt][0],af[mt][1],af[mt][2],af[mt][3],
                     bq[nt>>1][nt&1], bq[nt>>1][2+(nt&1)]);
    }
}

// A ldmatrix, B scalar (k-major)
template<int MT,int NT,int KS>
__device__ __forceinline__ void wtileLS(uint32_t aB,int ap,const uint32_t* B,int bp,
                                        float (&acc)[MT][NT][4], int cbase, int lane)
{
    int g = lane>>2, tg = lane&3;
#pragma unroll
    for (int ks=0;ks<KS;ks++){
        int k0 = ks*8;
        uint32_t af[MT][4];
#pragma unroll
        for (int mt=0;mt<MT;mt++)
            ldsm4(af[mt], aB + (uint32_t)((mt*16*ap + k0)*4));
        uint32_t bf[NT][2];
#pragma unroll
        for (int nt=0;nt<NT;nt++){
            int n = cbase + nt*8 + g;
            bf[nt][0] = B[(k0+tg)*bp + n];
            bf[nt][1] = B[(k0+tg+4)*bp + n];
        }
#pragma unroll
        for (int mt=0;mt<MT;mt++)
#pragma unroll
            for (int nt=0;nt<NT;nt++)
                mma8(acc[mt][nt], af[mt][0],af[mt][1],af[mt][2],af[mt][3],
                     bf[nt][0],bf[nt][1]);
    }
}

// fully scalar warp tile, A transposed in smem (A(row,k)=A[k*ap+row]); operands pre-tf32
template<int MT,int NT,int KS>
__device__ __forceinline__ void wtileS(const uint32_t* A,int ap,const uint32_t* B,int bp,
                                       float (&acc)[MT][NT][4], int rbase,int cbase,int lane)
{
    int g = lane>>2, tg = lane&3;
#pragma unroll
    for (int ks=0;ks<KS;ks++){
        int k0 = ks*8 + tg;
        uint32_t af[MT][4];
#pragma unroll
        for (int mt=0;mt<MT;mt++){
            int r0 = rbase + mt*16 + g;
            af[mt][0]=A[k0*ap + r0];
            af[mt][1]=A[k0*ap + r0+8];
            af[mt][2]=A[(k0+4)*ap + r0];
            af[mt][3]=A[(k0+4)*ap + r0+8];
        }
        uint32_t bf[NT][2];
#pragma unroll
        for (int nt=0;nt<NT;nt++){
            int n = cbase + nt*8 + g;
            bf[nt][0]=B[k0*bp + n];
            bf[nt][1]=B[(k0+4)*bp + n];
        }
#pragma unroll
        for (int mt=0;mt<MT;mt++)
#pragma unroll
            for (int nt=0;nt<NT;nt++)
                mma8(acc[mt][nt], af[mt][0],af[mt][1],af[mt][2],af[mt][3],
                     bf[nt][0],bf[nt][1]);
    }
}

// ---------------- transpose kernel (writes tf32-rounded fp32) ----------------
__global__ void __launch_bounds__(256) transpose_kernel(const float* __restrict__ in,
                                                        float* __restrict__ out,
                                                        int R, int Cc)
{
    __shared__ float t[32][33];
    int bx = blockIdx.x*32, by = blockIdx.y*32;
#pragma unroll
    for (int i=0;i<4;i++)
        t[threadIdx.y + 8*i][threadIdx.x] = in[(size_t)(by + threadIdx.y + 8*i)*Cc + bx + threadIdx.x];
    __syncthreads();
#pragma unroll
    for (int i=0;i<4;i++)
        out[(size_t)(bx + threadIdx.y + 8*i)*R + by + threadIdx.x] = f2tf32f(t[threadIdx.x][threadIdx.y + 8*i]);
}

// ---------------- K1: per-token rmsnorm + fused lr/gate projections ----------------
__global__ void __launch_bounds__(128) norm_kernel(const float* __restrict__ seq,
                                                   const float* __restrict__ ss,
                                                   const float* __restrict__ rs,
                                                   const float* __restrict__ w_ada,
                                                   const float* __restrict__ w_gate)
{
    int token = blockIdx.x;              // b*L + t
    int tid = threadIdx.x;
    int lane = tid & 31, w = tid >> 5;
    const float* x = seq + (size_t)token*DIMq;
    float v[4]; float acc = 0.f;
#pragma unroll
    for (int i=0;i<4;i++){ v[i] = x[tid + 128*i]; acc += v[i]*v[i]; }
#pragma unroll
    for (int off=16;off;off>>=1) acc += __shfl_xor_sync(0xffffffffu, acc, off);
    __shared__ float red[4];
    __shared__ float red8[4][8];
    if (lane==0) red[w] = acc;
    __syncthreads();
    float tot = red[0]+red[1]+red[2]+red[3];
    float rms = rsqrtf(tot*(1.f/DIMq) + EPSq);
    float p[8] = {0,0,0,0,0,0,0,0};
#pragma unroll
    for (int i=0;i<4;i++){
        int d = tid + 128*i;
        float y = v[i]*rms;
        float ysv = y*ss[d], yrv = y*rs[d];
        d_s_norm[(size_t)token*DIMq + d] = f2tf32f(ysv);
        d_r_norm[(size_t)token*DIMq + d] = f2tf32f(yrv);
#pragma unroll
        for (int h=0;h<4;h++){
            p[h]   += ysv*w_ada [d*4+h];
            p[4+h] += yrv*w_gate[d*4+h];
        }
    }
#pragma unroll
    for (int h=0;h<8;h++)
#pragma unroll
        for (int off=16;off;off>>=1) p[h] += __shfl_xor_sync(0xffffffffu, p[h], off);
    if (lane==0)
#pragma unroll
        for (int h=0;h<8;h++) red8[w][h] = p[h];
    __syncthreads();
    if (tid < 8){
        float s = red8[0][tid]+red8[1][tid]+red8[2][tid]+red8[3][tid];
        int b = token >> 12, t = token & (Lq-1);
        if (tid < 4)
            d_lr[((size_t)(b*Hq+tid))*Lq + t] = sigm(s)*MAXLR;
        else if (t >= Cq-1)
            d_gatev[((size_t)b*Lq + (t-(Cq-1)))*Hq + (tid-4)] = sigm(s);
    }
}

// ---------------- chunk means of s ----------------
__global__ void __launch_bounds__(512) chunk_mean_kernel()
{
    int bn = blockIdx.x;            // b*N + n
    int d = threadIdx.x;
    int b = bn / Nq, n = bn % Nq;
    const float* base = d_s_norm + ((size_t)b*Lq + n*Cq)*DIMq + d;
    float acc = 0.f;
#pragma unroll 8
    for (int c=0;c<Cq;c++) acc += base[(size_t)c*DIMq];
    d_seqmean[(size_t)bn*DIMq + d] = acc*(1.f/Cq);
}

// ---------------- ada_mom / decay from seq_mean ----------------
__global__ void momdec_kernel(const float* __restrict__ wm, const float* __restrict__ wd)
{
    int warp = (blockIdx.x*blockDim.x + threadIdx.x) >> 5;
    int lane = threadIdx.x & 31;
    if (warp >= Bq*Nq) return;
    const float* x = d_seqmean + (size_t)warp*DIMq;
    float a[4]={0,0,0,0}, b4[4]={0,0,0,0};
    for (int d=lane; d<DIMq; d+=32){
        float xv = x[d];
#pragma unroll
        for (int h=0;h<4;h++){ a[h]+=xv*wm[d*4+h]; b4[h]+=xv*wd[d*4+h]; }
    }
#pragma unroll
    for (int off=16;off;off>>=1)
#pragma unroll
        for (int h=0;h<4;h++){
            a[h]  += __shfl_down_sync(0xffffffffu,a[h],off);
            b4[h] += __shfl_down_sync(0xffffffffu,b4[h],off);
        }
    if (lane==0){
        int b = warp / Nq, n = warp % Nq;
#pragma unroll
        for (int h=0;h<4;h++){
            d_am[(size_t)(b*Hq+h)*Nq + n] = sigm(a[h]);
            d_dc[(size_t)(b*Hq+h)*Nq + n] = sigm(b4[h]);
        }
    }
}

// ---------------- big GEMM, tf32 TC, cp.async 3-stage pipeline ----------------
#define GAP 36
#define GBP 36
#define GSTG (128*GAP + 64*GBP)
template<int MODE>
__global__ void __launch_bounds__(256) gemm_tc(const float* __restrict__ A,
                                               const float* __restrict__ WT,
                                               float* __restrict__ out0,
                                               float* __restrict__ out1,
                                               int K)
{
    extern __shared__ uint32_t sh[];
    uint32_t shAddr = (uint32_t)__cvta_generic_to_shared(sh);
    int tid = threadIdx.x, lane = tid & 31, wid = tid >> 5;
    int wm = wid >> 1, wn = wid & 1;       // 4 x 2 warps, 32x32 tiles
    int m0 = blockIdx.y*128, n0 = blockIdx.x*64;
    float acc[2][4][4] = {};
    int ar = tid>>3, ac4 = tid&7;          // A: rows ar+32i (i<4), 16B col ac4
    int bn = tid>>3, bk4 = tid&7;          // B: n-rows bn+32i (i<2)

    const int NK = K/32;
    auto issue = [&](int kt){
        int k0 = kt*32;
        uint32_t aB = shAddr + (uint32_t)((kt%3)*GSTG*4);
        uint32_t bB = aB + 128*GAP*4;
#pragma unroll
        for (int i=0;i<4;i++){
            int gr = m0 + ar + 32*i;
            uint32_t d = aB + (uint32_t)(((ar+32*i)*GAP + ac4*4)*4);
            if (MODE==1){
                int t = gr & (Lq-1);
                cpa16z(d, &A[(size_t)(gr+Cq-1)*K + k0 + ac4*4], t <= Lq-Cq);
            } else {
                cpa16(d, &A[(size_t)gr*K + k0 + ac4*4]);
            }
        }
#pragma unroll
        for (int i=0;i<2;i++)
            cpa16(bB + (uint32_t)(((bn+32*i)*GBP + bk4*4)*4),
                  &WT[(size_t)(n0 + bn + 32*i)*K + k0 + bk4*4]);
        cpcommit();
    };

    issue(0);
    if (NK>1) issue(1);
#pragma unroll 1
    for (int kt=0; kt<NK; kt++){
        if (kt == NK-1) cpwait<0>(); else cpwait<1>();
        __syncthreads();
        if (kt+2 < NK) issue(kt+2);
        uint32_t aB = shAddr + (uint32_t)((kt%3)*GSTG*4);
        uint32_t bB = aB + 128*GAP*4;
        wtileLL<2,4,4>(ldsmBase(aB, wm*32, GAP, lane), GAP,
                       ldsmBase(bB, wn*32, GBP, lane), GBP, acc);
        __syncthreads();
    }

    int g = lane>>2, tg = lane&3;
#pragma unroll
    for (int mt=0;mt<2;mt++)
#pragma unroll
    for (int nt=0;nt<4;nt++)
#pragma unroll
    for (int e=0;e<4;e++){
        int row = m0 + wm*32 + mt*16 + g + ((e&2)?8:0);
        int col = n0 + wn*32 + nt*8 + 2*tg + (e&1);
        float v = acc[mt][nt][e];
        int b = row >> 12, t = row & (Lq-1);
        if (MODE==0){
            if (col < Hq*DHq){
                int h = col>>7, d = col&127;
                out0[((size_t)(b*Hq+h)*Lq + t)*DHq + d] = f2tf32f(v);   // keys (tf32)
            } else {
                int c2 = col - Hq*DHq; int h = c2>>7, d = c2&127;
                out1[((size_t)(b*Hq+h)*Lq + t)*DHq + d] = v;            // vals fp32
            }
        } else if (MODE==1){
            int h = col>>7, d = col&127;
            out0[((size_t)(b*Hq+h)*Lq + t)*DHq + d] = f2tf32f(v);       // quer (tf32)
        } else {
            if (t <= Lq - Cq)
                out0[((size_t)b*Lq + t + Cq - 1)*DIMq + col] = v;       // final out fp32
        }
    }
}

// ---------------- per-chunk kernels ----------------
#define PT 132

// ---------------- chunk gradient ----------------
__global__ void __launch_bounds__(256) chunk_grad_kernel()
{
    extern __shared__ uint32_t smu[];
    uint32_t* Ks = smu;            // 64*PT keys (tf32)
    uint32_t* Ab = Ks + 64*PT;     // a=silu(h) (tf32), later dh
    uint32_t* Db = Ab + 64*PT;     // v (fp32), later dpred (tf32)
    uint32_t* Ws = Db + 64*PT;     // 128*PT weights (w0T, then w1T)
    float* Lr = (float*)(Ws + 128*PT);
    uint32_t KsA = (uint32_t)__cvta_generic_to_shared(Ks);
    uint32_t AbA = (uint32_t)__cvta_generic_to_shared(Ab);
    uint32_t DbA = (uint32_t)__cvta_generic_to_shared(Db);
    uint32_t WsA = (uint32_t)__cvta_generic_to_shared(Ws);
    int tid = threadIdx.x, lane = tid&31, wid = tid>>5;
    int wm = wid>>2, wn = wid&3;   // 2 x 4 warps
    int g = lane>>2, tg = lane&3;
    int chunk = blockIdx.x;
    int bh = chunk >> 6, t0 = (chunk & 63) << 6;

    const float* kg = d_keys + ((size_t)bh*Lq + t0)*DHq;
    const float* vg = d_vals + ((size_t)bh*Lq + t0)*DHq;
#pragma unroll
    for (int u=tid; u<2048; u+=256){
        int r = u>>5, c = (u&31)*4;
        cpa16(KsA + (r*PT+c)*4, kg + u*4);
        cpa16(DbA + (r*PT+c)*4, vg + u*4);
    }
#pragma unroll
    for (int u=tid; u<4096; u+=256){
        int r = u>>5, c = (u&31)*4;
        cpa16(WsA + (r*PT+c)*4, d_w0T + u*4);
    }
    cpcommit();
    if (tid < 64) Lr[tid] = d_lr[(size_t)bh*Lq + t0 + tid];
    cpwait<0>();
    __syncthreads();

    // h = K @ w0 (B n-major = w0T); h kept in regs; a = silu(h) -> Ab
    float hreg[2][4][4] = {};
    wtileLL<2,4,16>(ldsmBase(KsA, wm*32, PT, lane), PT,
                    ldsmBase(WsA, wn*32, PT, lane), PT, hreg);
#pragma unroll
    for (int mt=0;mt<2;mt++)
#pragma unroll
    for (int nt=0;nt<4;nt++)
#pragma unroll
    for (int e=0;e<4;e++){
        int row = wm*32 + mt*16 + g + ((e&2)?8:0);
        int col = wn*32 + nt*8 + 2*tg + (e&1);
        float h = hreg[mt][nt][e];
        Ab[row*PT+col] = f2tf32(h/(1.f+expf(-h)));
    }
    __syncthreads();
#pragma unroll
    for (int u=tid; u<4096; u+=256){
        int r = u>>5, c = (u&31)*4;
        cpa16(WsA + (r*PT+c)*4, d_w1T + u*4);
    }
    cpcommit(); cpwait<0>();
    __syncthreads();

    {   // pred = a @ w1 ; dpred = lr*2/DH*(pred-v) -> Db (tf32)
        float acc[2][4][4] = {};
        wtileLL<2,4,16>(ldsmBase(AbA, wm*32, PT, lane), PT,
                        ldsmBase(WsA, wn*32, PT, lane), PT, acc);
#pragma unroll
        for (int mt=0;mt<2;mt++)
#pragma unroll
        for (int nt=0;nt<4;nt++)
#pragma unroll
        for (int e=0;e<4;e++){
            int row = wm*32 + mt*16 + g + ((e&2)?8:0);
            int col = wn*32 + nt*8 + 2*tg + (e&1);
            float v = __uint_as_float(Db[row*PT+col]);
            Db[row*PT+col] = f2tf32(Lr[row]*(2.f/DHq)*(acc[mt][nt][e] - v));
        }
    }
    __syncthreads();

    {   // g1^T = dpred^T @ a -> gmem (transposed layout)
        float acc[4][4][4] = {};
        wtileS<4,4,8>(Db, PT, Ab, PT, acc, wm*64, wn*32, lane);
        float* G = d_g1 + (size_t)chunk*DHq*DHq;
#pragma unroll
        for (int mt=0;mt<4;mt++)
#pragma unroll
        for (int nt=0;nt<4;nt++){
            int row = wm*64 + mt*16 + g;
            int col = wn*32 + nt*8 + 2*tg;
            *(float2*)&G[row*DHq + col]     = make_float2(acc[mt][nt][0], acc[mt][nt][1]);
            *(float2*)&G[(row+8)*DHq + col] = make_float2(acc[mt][nt][2], acc[mt][nt][3]);
        }
    }
    __syncthreads();

    {   // da = dpred @ w1^T (B k-major scalar from Ws) ; dh = da*dsilu(h) -> Ab
        float acc[2][4][4] = {};
        wtileLS<2,4,16>(ldsmBase(DbA, wm*32, PT, lane), PT, Ws, PT, acc, wn*32, lane);
#pragma unroll
        for (int mt=0;mt<2;mt++)
#pragma unroll
        for (int nt=0;nt<4;nt++)
#pragma unroll
        for (int e=0;e<4;e++){
            int row = wm*32 + mt*16 + g + ((e&2)?8:0);
            int col = wn*32 + nt*8 + 2*tg + (e&1);
            float h = hreg[mt][nt][e];
            float s = 1.f/(1.f+expf(-h));
            Ab[row*PT+col] = f2tf32(acc[mt][nt][e] * s * (1.f + h*(1.f - s)));
        }
    }
    __syncthreads();

    {   // g0^T = dh^T @ K -> gmem (transposed layout)
        float acc[4][4][4] = {};
        wtileS<4,4,8>(Ab, PT, Ks, PT, acc, wm*64, wn*32, lane);
        float* G = d_g0 + (size_t)chunk*DHq*DHq;
#pragma unroll
        for (int mt=0;mt<4;mt++)
#pragma unroll
        for (int nt=0;nt<4;nt++){
            int row = wm*64 + mt*16 + g;
            int col = wn*32 + nt*8 + 2*tg;
            *(float2*)&G[row*DHq + col]     = make_float2(acc[mt][nt][0], acc[mt][nt][1]);
            *(float2*)&G[(row+8)*DHq + col] = make_float2(acc[mt][nt][2], acc[mt][nt][3]);
        }
    }
}

// ---------------- scan (transposed layout; writes tf32-rounded) ----------------
__global__ void __launch_bounds__(256) scan_kernel()
{
    __shared__ float ams[Nq], dcs[Nq];
    int gid = blockIdx.x*256 + threadIdx.x;
    int bh = gid >> 14;
    int e  = gid & 16383;
    if (threadIdx.x < Nq){
        ams[threadIdx.x] = d_am[(size_t)bh*Nq + threadIdx.x];
        dcs[threadIdx.x] = d_dc[(size_t)bh*Nq + threadIdx.x];
    }
    __syncthreads();
    float m0=0.f,u0=0.f,m1=0.f,u1=0.f;
    float wa = d_w0T[e], wb = d_w1T[e];
    size_t base = ((size_t)bh*Nq)*16384 + e;
    for (int n=0;n<Nq;n++){
        float a = ams[n], d = 1.f - dcs[n];
        size_t off = base + (size_t)n*16384;
        m0 = a*m0 - d_g0[off];  u0 = d*u0 + m0;  d_w0t[off] = f2tf32f(wa + u0);
        m1 = a*m1 - d_g1[off];  u1 = d*u1 + m1;  d_w1t[off] = f2tf32f(wb + u1);
    }
}

// ---------------- retrieve MLP + RMSNorm + gate ----------------
__global__ void __launch_bounds__(256) retrieve_kernel(const float* __restrict__ gamma)
{
    extern __shared__ uint32_t smr[];
    uint32_t* Qs  = smr;            // q (tf32), later o (fp32)
    uint32_t* Ab  = Qs + 64*PT;     // a (tf32)
    uint32_t* Ws0 = Ab + 64*PT;     // 128*PT w0t
    uint32_t* Ws1 = Ws0 + 128*PT;   // 128*PT w1t
    uint32_t QsA  = (uint32_t)__cvta_generic_to_shared(Qs);
    uint32_t AbA  = (uint32_t)__cvta_generic_to_shared(Ab);
    uint32_t Ws0A = (uint32_t)__cvta_generic_to_shared(Ws0);
    uint32_t Ws1A = (uint32_t)__cvta_generic_to_shared(Ws1);
    int tid = threadIdx.x, lane = tid&31, wid = tid>>5;
    int wm = wid>>2, wn = wid&3;
    int g = lane>>2, tg = lane&3;
    int chunk = blockIdx.x;
    int bh = chunk >> 6, n = chunk & 63;
    int b = bh >> 2, h = bh & 3;

    const float* qg  = d_quer + ((size_t)bh*Lq + n*Cq)*DHq;
    const float* w0c = d_w0t + (size_t)chunk*DHq*DHq;
    const float* w1c = d_w1t + (size_t)chunk*DHq*DHq;
#pragma unroll
    for (int u=tid; u<2048; u+=256){
        int r = u>>5, c = (u&31)*4;
        cpa16(QsA + (r*PT+c)*4, qg + u*4);
    }
#pragma unroll
    for (int u=tid; u<4096; u+=256){
        int r = u>>5, c = (u&31)*4;
        cpa16(Ws0A + (r*PT+c)*4, w0c + u*4);
    }
    cpcommit();
#pragma unroll
    for (int u=tid; u<4096; u+=256){
        int r = u>>5, c = (u&31)*4;
        cpa16(Ws1A + (r*PT+c)*4, w1c + u*4);
    }
    cpcommit();
    cpwait<1>();               // q + w0t ready
    __syncthreads();

    {   // a = silu(q @ w0_t)
        float acc[2][4][4] = {};
        wtileLL<2,4,16>(ldsmBase(QsA, wm*32, PT, lane), PT,
                        ldsmBase(Ws0A, wn*32, PT, lane), PT, acc);
#pragma unroll
        for (int mt=0;mt<2;mt++)
#pragma unroll
        for (int nt=0;nt<4;nt++)
#pragma unroll
        for (int e=0;e<4;e++){
            int row = wm*32 + mt*16 + g + ((e&2)?8:0);
            int col = wn*32 + nt*8 + 2*tg + (e&1);
            float hh = acc[mt][nt][e];
            Ab[row*PT+col] = f2tf32(hh/(1.f+expf(-hh)));
        }
    }
    cpwait<0>();               // w1t ready
    __syncthreads();

    {   // o = a @ w1_t into Qs (fp32 bits)
        float acc[2][4][4] = {};
        wtileLL<2,4,16>(ldsmBase(AbA, wm*32, PT, lane), PT,
                        ldsmBase(Ws1A, wn*32, PT, lane), PT, acc);
        __syncthreads();
#pragma unroll
        for (int mt=0;mt<2;mt++)
#pragma unroll
        for (int nt=0;nt<4;nt++)
#pragma unroll
        for (int e=0;e<4;e++){
            int row = wm*32 + mt*16 + g + ((e&2)?8:0);
            int col = wn*32 + nt*8 + 2*tg + (e&1);
            Qs[row*PT+col] = __float_as_uint(acc[mt][nt][e]);
        }
    }
    __syncthreads();

    const float* Of = (const float*)Qs;
    int w = tid >> 5;
#pragma unroll
    for (int rr=0; rr<8; rr++){
        int row = w*8 + rr;
        float v0 = Of[row*PT + lane];
        float v1 = Of[row*PT + lane + 32];
        float v2 = Of[row*PT + lane + 64];
        float v3 = Of[row*PT + lane + 96];
        float ss = v0*v0 + v1*v1 + v2*v2 + v3*v3;
#pragma unroll
        for (int off=16;off;off>>=1) ss += __shfl_xor_sync(0xffffffffu, ss, off);
        float sc = rsqrtf(ss*(1.f/DHq) + EPSq);
        int t = n*Cq + row;
        float gt = d_gatev[((size_t)b*Lq + t)*Hq + h];
        float* dst = d_comb + ((size_t)b*Lq + t)*DIMq + h*DHq;
        dst[lane     ] = f2tf32f(v0*sc*(gamma[h*DHq + lane     ] + 1.f)*gt);
        dst[lane + 32] = f2tf32f(v1*sc*(gamma[h*DHq + lane + 32] + 1.f)*gt);
        dst[lane + 64] = f2tf32f(v2*sc*(gamma[h*DHq + lane + 64] + 1.f)*gt);
        dst[lane + 96] = f2tf32f(v3*sc*(gamma[h*DHq + lane + 96] + 1.f)*gt);
    }
}

// ---------------- empty-embed fill ----------------
__global__ void empty_fill_kernel(const float* __restrict__ emb, float* __restrict__ out)
{
    int gid = blockIdx.x*blockDim.x + threadIdx.x;
    int total = Bq*(Cq-1)*DIMq;
    if (gid >= total) return;
    int d = gid & (DIMq-1);
    int row = gid / DIMq;
    int b = row / (Cq-1), t = row % (Cq-1);
    out[((size_t)b*Lq + t)*DIMq + d] = emb[d];
}

// ---------------- launch ----------------
extern "C" void kernel_launch(void* const* d_in, const int* in_sizes, int n_in,
                              void* d_out, int out_size)
{
    const float* seq      = (const float*)d_in[0];
    const float* ss       = (const float*)d_in[1];
    const float* rs       = (const float*)d_in[2];
    const float* w_q      = (const float*)d_in[3];
    const float* w_kv     = (const float*)d_in[4];
    const float* w_ada    = (const float*)d_in[5];
    const float* w_mom    = (const float*)d_in[6];
    const float* w_dec    = (const float*)d_in[7];
    const float* w0       = (const float*)d_in[8];
    const float* w1       = (const float*)d_in[9];
    const float* gamma    = (const float*)d_in[10];
    const float* w_gate   = (const float*)d_in[11];
    const float* w_comb   = (const float*)d_in[12];
    const float* emb      = (const float*)d_in[13];
    float* out = (float*)d_out;

    float *p_snorm, *p_rnorm, *p_keys, *p_vals, *p_quer, *p_comb;
    float *p_wkvT, *p_wqT, *p_wcT, *p_w0T, *p_w1T;
    cudaGetSymbolAddress((void**)&p_snorm, d_s_norm);
    cudaGetSymbolAddress((void**)&p_rnorm, d_r_norm);
    cudaGetSymbolAddress((void**)&p_keys,  d_keys);
    cudaGetSymbolAddress((void**)&p_vals,  d_vals);
    cudaGetSymbolAddress((void**)&p_quer,  d_quer);
    cudaGetSymbolAddress((void**)&p_comb,  d_comb);
    cudaGetSymbolAddress((void**)&p_wkvT,  d_wkvT);
    cudaGetSymbolAddress((void**)&p_wqT,   d_wqT);
    cudaGetSymbolAddress((void**)&p_wcT,   d_wcT);
    cudaGetSymbolAddress((void**)&p_w0T,   d_w0T);
    cudaGetSymbolAddress((void**)&p_w1T,   d_w1T);

    const int SMEM_GEMM = 3*GSTG*4;                        // 82944 B
    const int SMEM_G = (3*64*PT + 128*PT)*4 + 256;         // 169216 B
    const int SMEM_R = (2*64*PT + 2*128*PT)*4;             // 202752 B
    cudaFuncSetAttribute(gemm_tc<0>, cudaFuncAttributeMaxDynamicSharedMemorySize, SMEM_GEMM);
    cudaFuncSetAttribute(gemm_tc<1>, cudaFuncAttributeMaxDynamicSharedMemorySize, SMEM_GEMM);
    cudaFuncSetAttribute(gemm_tc<2>, cudaFuncAttributeMaxDynamicSharedMemorySize, SMEM_GEMM);
    cudaFuncSetAttribute(chunk_grad_kernel, cudaFuncAttributeMaxDynamicSharedMemorySize, SMEM_G);
    cudaFuncSetAttribute(retrieve_kernel,   cudaFuncAttributeMaxDynamicSharedMemorySize, SMEM_R);

    // fork/join streams (capture-safe)
    cudaStream_t s1, s2;
    cudaStreamCreateWithFlags(&s1, cudaStreamNonBlocking);
    cudaStreamCreateWithFlags(&s2, cudaStreamNonBlocking);
    cudaEvent_t e0, et, en, eq, em;
    cudaEventCreateWithFlags(&e0, cudaEventDisableTiming);
    cudaEventCreateWithFlags(&et, cudaEventDisableTiming);
    cudaEventCreateWithFlags(&en, cudaEventDisableTiming);
    cudaEventCreateWithFlags(&eq, cudaEventDisableTiming);
    cudaEventCreateWithFlags(&em, cudaEventDisableTiming);

    cudaEventRecord(e0, 0);
    cudaStreamWaitEvent(s1, e0, 0);
    cudaStreamWaitEvent(s2, e0, 0);

    // s1: weight transposes + empty fill
    transpose_kernel<<<dim3(1024/32, 512/32), dim3(32,8), 0, s1>>>(w_kv,   p_wkvT, DIMq, 2*Hq*DHq);
    transpose_kernel<<<dim3(512/32,  512/32), dim3(32,8), 0, s1>>>(w_q,    p_wqT,  DIMq, Hq*DHq);
    transpose_kernel<<<dim3(512/32,  512/32), dim3(32,8), 0, s1>>>(w_comb, p_wcT,  Hq*DHq, DIMq);
    transpose_kernel<<<dim3(4,4),             dim3(32,8), 0, s1>>>(w0,     p_w0T,  DHq, DHq);
    transpose_kernel<<<dim3(4,4),             dim3(32,8), 0, s1>>>(w1,     p_w1T,  DHq, DHq);
    empty_fill_kernel<<<(Bq*(Cq-1)*DIMq + 255)/256, 256, 0, s1>>>(emb, out);
    cudaEventRecord(et, s1);

    // main: rmsnorms + fused projections
    norm_kernel<<<Bq*Lq, 128>>>(seq, ss, rs, w_ada, w_gate);
    cudaEventRecord(en, 0);

    // s1: chunk means -> momdec
    cudaStreamWaitEvent(s1, en, 0);
    chunk_mean_kernel<<<Bq*Nq, 512, 0, s1>>>();
    momdec_kernel<<<(Bq*Nq*32 + 255)/256, 256, 0, s1>>>(w_mom, w_dec);
    cudaEventRecord(em, s1);

    // s2: query projection
    cudaStreamWaitEvent(s2, en, 0);
    cudaStreamWaitEvent(s2, et, 0);
    gemm_tc<1><<<dim3((Hq*DHq)/64, (Bq*Lq)/128), 256, SMEM_GEMM, s2>>>(p_rnorm, p_wqT, p_quer, nullptr, DIMq);
    cudaEventRecord(eq, s2);

    // main chain
    cudaStreamWaitEvent(0, et, 0);
    gemm_tc<0><<<dim3((2*Hq*DHq)/64, (Bq*Lq)/128), 256, SMEM_GEMM>>>(p_snorm, p_wkvT, p_keys, p_vals, DIMq);
    chunk_grad_kernel<<<NCHUNK, 256, SMEM_G>>>();
    cudaStreamWaitEvent(0, em, 0);
    scan_kernel<<<(BHq*16384)/256, 256>>>();
    cudaStreamWaitEvent(0, eq, 0);
    retrieve_kernel<<<NCHUNK, 256, SMEM_R>>>(gamma);
    gemm_tc<2><<<dim3(DIMq/64, (Bq*Lq)/128), 256, SMEM_GEMM>>>(p_comb, p_wcT, out, nullptr, Hq*DHq);

    cudaStreamCaptureStatus cap = cudaStreamCaptureStatusNone;
    cudaStreamIsCapturing(0, &cap);
    if (cap == cudaStreamCaptureStatusNone){
        cudaStreamDestroy(s1); cudaStreamDestroy(s2);
        cudaEventDestroy(e0); cudaEventDestroy(et); cudaEventDestroy(en);
        cudaEventDestroy(eq); cudaEventDestroy(em);
    }
}

// round 6
// speedup vs baseline: 3.4603x; 1.0234x over previous
#include <cuda_runtime.h>
#include <cuda_bf16.h>
#include <math.h>
#include <stdint.h>

// ---------------- problem constants ----------------
#define Bq   2
#define Lq   4096
#define DIMq 512
#define Hq   4
#define DHq  128
#define Cq   64
#define Nq   64          // L / C
#define BHq  8           // B * H
#define NCHUNK 512       // BH * N
#define MAXLR 0.01f
#define EPSq  1e-6f

// ---------------- scratch (device globals; allocation-free) ----------------
// buffers marked (tf32) hold fp32 values pre-rounded to tf32.
__device__ float d_s_norm[Bq*Lq*DIMq];       // (tf32)
__device__ float d_r_norm[Bq*Lq*DIMq];       // (tf32)
__device__ float d_keys  [BHq*Lq*DHq];       // (tf32)
__device__ float d_vals  [BHq*Lq*DHq];       // fp32
__device__ float d_quer  [BHq*Lq*DHq];       // (tf32)
__device__ float d_lr    [BHq*Lq];
__device__ float d_seqmean[Bq*Nq*DIMq];
__device__ float d_am    [BHq*Nq];
__device__ float d_dc    [BHq*Nq];
__device__ float d_g0    [NCHUNK*DHq*DHq];   // fp32, TRANSPOSED layout
__device__ float d_g1    [NCHUNK*DHq*DHq];   // fp32, TRANSPOSED layout
__device__ float d_w0t   [NCHUNK*DHq*DHq];   // (tf32), TRANSPOSED layout
__device__ float d_w1t   [NCHUNK*DHq*DHq];   // (tf32), TRANSPOSED layout
__device__ float d_comb  [Bq*Lq*DIMq];       // (tf32)
__device__ float d_gatev [Bq*Lq*Hq];
// pretransposed weights, (tf32)
__device__ float d_wkvT[2*Hq*DHq*DIMq];
__device__ float d_wqT [Hq*DHq*DIMq];
__device__ float d_wcT [DIMq*Hq*DHq];
__device__ float d_w0T [DHq*DHq];
__device__ float d_w1T [DHq*DHq];

__device__ __forceinline__ float sigm(float x){ return 1.f/(1.f+expf(-x)); }

// ---------------- tf32 mma primitives ----------------
__device__ __forceinline__ uint32_t f2tf32(float x){
    uint32_t r; asm("cvt.rna.tf32.f32 %0, %1;" : "=r"(r) : "f"(x)); return r;
}
__device__ __forceinline__ float f2tf32f(float x){ return __uint_as_float(f2tf32(x)); }

__device__ __forceinline__ void mma8(float (&c)[4],
                                     uint32_t a0,uint32_t a1,uint32_t a2,uint32_t a3,
                                     uint32_t b0,uint32_t b1){
    asm volatile("mma.sync.aligned.m16n8k8.row.col.f32.tf32.tf32.f32 "
        "{%0,%1,%2,%3},{%4,%5,%6,%7},{%8,%9},{%0,%1,%2,%3};"
        : "+f"(c[0]),"+f"(c[1]),"+f"(c[2]),"+f"(c[3])
        : "r"(a0),"r"(a1),"r"(a2),"r"(a3),"r"(b0),"r"(b1));
}

__device__ __forceinline__ void ldsm4(uint32_t* r, uint32_t addr){
    asm volatile("ldmatrix.sync.aligned.m8n8.x4.shared.b16 {%0,%1,%2,%3}, [%4];"
        : "=r"(r[0]),"=r"(r[1]),"=r"(r[2]),"=r"(r[3]) : "r"(addr));
}

__device__ __forceinline__ uint32_t ldsmBase(uint32_t shAddr, int rbase, int ap, int lane){
    return shAddr + (uint32_t)(((rbase + (lane&15))*ap + ((lane>>4)<<2))*4);
}

// ---------------- cp.async helpers ----------------
__device__ __forceinline__ void cpa16(uint32_t dst, const float* src){
    asm volatile("cp.async.ca.shared.global [%0],[%1],16;"::"r"(dst),"l"(src));
}
__device__ __forceinline__ void cpa16z(uint32_t dst, const float* src, bool p){
    int sz = p ? 16 : 0;
    asm volatile("cp.async.ca.shared.global [%0],[%1],16,%2;"::"r"(dst),"l"(src),"r"(sz));
}
__device__ __forceinline__ void cpcommit(){ asm volatile("cp.async.commit_group;"); }
template<int N> __device__ __forceinline__ void cpwait(){ asm volatile("cp.async.wait_group %0;"::"n"(N)); }

// both-side ldmatrix warp tile
template<int MT,int NT,int KS>
__device__ __forceinline__ void wtileLL(uint32_t aB,int ap,uint32_t bB,int bp,
                                        float (&acc)[MT][NT][4])
{
#pragma unroll
    for (int ks=0;ks<KS;ks++){
        int k0 = ks*8;
        uint32_t af[MT][4];
#pragma unroll
        for (int mt=0;mt<MT;mt++)
            ldsm4(af[mt], aB + (uint32_t)((mt*16*ap + k0)*4));
        uint32_t bq[NT/2][4];
#pragma unroll
        for (int nt2=0;nt2<NT/2;nt2++)
            ldsm4(bq[nt2], bB + (uint32_t)((nt2*16*bp + k0)*4));
#pragma unroll
        for (int mt=0;mt<MT;mt++)
#pragma unroll
            for (int nt=0;nt<NT;nt++)
                mma8(acc[mt][nt], af[mt][0],af[mt][1],af[mt][2],af[mt][3],
                     bq[nt>>1][nt&1], bq[nt>>1][2+(nt&1)]);
    }
}

// A ldmatrix, B scalar (k-major)
template<int MT,int NT,int KS>
__device__ __forceinline__ void wtileLS(uint32_t aB,int ap,const uint32_t* B,int bp,
                                        float (&acc)[MT][NT][4], int cbase, int lane)
{
    int g = lane>>2, tg = lane&3;
#pragma unroll
    for (int ks=0;ks<KS;ks++){
        int k0 = ks*8;
        uint32_t af[MT][4];
#pragma unroll
        for (int mt=0;mt<MT;mt++)
            ldsm4(af[mt], aB + (uint32_t)((mt*16*ap + k0)*4));
        uint32_t bf[NT][2];
#pragma unroll
        for (int nt=0;nt<NT;nt++){
            int n = cbase + nt*8 + g;
            bf[nt][0] = B[(k0+tg)*bp + n];
            bf[nt][1] = B[(k0+tg+4)*bp + n];
        }
#pragma unroll
        for (int mt=0;mt<MT;mt++)
#pragma unroll
            for (int nt=0;nt<NT;nt++)
                mma8(acc[mt][nt], af[mt][0],af[mt][1],af[mt][2],af[mt][3],
                     bf[nt][0],bf[nt][1]);
    }
}

// ---------------- transpose kernel (writes tf32-rounded fp32) ----------------
__global__ void __launch_bounds__(256) transpose_kernel(const float* __restrict__ in,
                                                        float* __restrict__ out,
                                                        int R, int Cc)
{
    __shared__ float t[32][33];
    int bx = blockIdx.x*32, by = blockIdx.y*32;
#pragma unroll
    for (int i=0;i<4;i++)
        t[threadIdx.y + 8*i][threadIdx.x] = in[(size_t)(by + threadIdx.y + 8*i)*Cc + bx + threadIdx.x];
    __syncthreads();
#pragma unroll
    for (int i=0;i<4;i++)
        out[(size_t)(bx + threadIdx.y + 8*i)*R + by + threadIdx.x] = f2tf32f(t[threadIdx.x][threadIdx.y + 8*i]);
}

// ---------------- K1: per-token rmsnorm + fused lr/gate projections ----------------
__global__ void __launch_bounds__(128) norm_kernel(const float* __restrict__ seq,
                                                   const float* __restrict__ ss,
                                                   const float* __restrict__ rs,
                                                   const float* __restrict__ w_ada,
                                                   const float* __restrict__ w_gate)
{
    int token = blockIdx.x;              // b*L + t
    int tid = threadIdx.x;
    int lane = tid & 31, w = tid >> 5;
    const float* x = seq + (size_t)token*DIMq;
    float v[4]; float acc = 0.f;
#pragma unroll
    for (int i=0;i<4;i++){ v[i] = x[tid + 128*i]; acc += v[i]*v[i]; }
#pragma unroll
    for (int off=16;off;off>>=1) acc += __shfl_xor_sync(0xffffffffu, acc, off);
    __shared__ float red[4];
    __shared__ float red8[4][8];
    if (lane==0) red[w] = acc;
    __syncthreads();
    float tot = red[0]+red[1]+red[2]+red[3];
    float rms = rsqrtf(tot*(1.f/DIMq) + EPSq);
    float p[8] = {0,0,0,0,0,0,0,0};
#pragma unroll
    for (int i=0;i<4;i++){
        int d = tid + 128*i;
        float y = v[i]*rms;
        float ysv = y*ss[d], yrv = y*rs[d];
        d_s_norm[(size_t)token*DIMq + d] = f2tf32f(ysv);
        d_r_norm[(size_t)token*DIMq + d] = f2tf32f(yrv);
#pragma unroll
        for (int h=0;h<4;h++){
            p[h]   += ysv*w_ada [d*4+h];
            p[4+h] += yrv*w_gate[d*4+h];
        }
    }
#pragma unroll
    for (int h=0;h<8;h++)
#pragma unroll
        for (int off=16;off;off>>=1) p[h] += __shfl_xor_sync(0xffffffffu, p[h], off);
    if (lane==0)
#pragma unroll
        for (int h=0;h<8;h++) red8[w][h] = p[h];
    __syncthreads();
    if (tid < 8){
        float s = red8[0][tid]+red8[1][tid]+red8[2][tid]+red8[3][tid];
        int b = token >> 12, t = token & (Lq-1);
        if (tid < 4)
            d_lr[((size_t)(b*Hq+tid))*Lq + t] = sigm(s)*MAXLR;
        else if (t >= Cq-1)
            d_gatev[((size_t)b*Lq + (t-(Cq-1)))*Hq + (tid-4)] = sigm(s);
    }
}

// ---------------- chunk means of s ----------------
__global__ void __launch_bounds__(512) chunk_mean_kernel()
{
    int bn = blockIdx.x;            // b*N + n
    int d = threadIdx.x;
    int b = bn / Nq, n = bn % Nq;
    const float* base = d_s_norm + ((size_t)b*Lq + n*Cq)*DIMq + d;
    float acc = 0.f;
#pragma unroll 8
    for (int c=0;c<Cq;c++) acc += base[(size_t)c*DIMq];
    d_seqmean[(size_t)bn*DIMq + d] = acc*(1.f/Cq);
}

// ---------------- ada_mom / decay from seq_mean ----------------
__global__ void momdec_kernel(const float* __restrict__ wm, const float* __restrict__ wd)
{
    int warp = (blockIdx.x*blockDim.x + threadIdx.x) >> 5;
    int lane = threadIdx.x & 31;
    if (warp >= Bq*Nq) return;
    const float* x = d_seqmean + (size_t)warp*DIMq;
    float a[4]={0,0,0,0}, b4[4]={0,0,0,0};
    for (int d=lane; d<DIMq; d+=32){
        float xv = x[d];
#pragma unroll
        for (int h=0;h<4;h++){ a[h]+=xv*wm[d*4+h]; b4[h]+=xv*wd[d*4+h]; }
    }
#pragma unroll
    for (int off=16;off;off>>=1)
#pragma unroll
        for (int h=0;h<4;h++){
            a[h]  += __shfl_down_sync(0xffffffffu,a[h],off);
            b4[h] += __shfl_down_sync(0xffffffffu,b4[h],off);
        }
    if (lane==0){
        int b = warp / Nq, n = warp % Nq;
#pragma unroll
        for (int h=0;h<4;h++){
            d_am[(size_t)(b*Hq+h)*Nq + n] = sigm(a[h]);
            d_dc[(size_t)(b*Hq+h)*Nq + n] = sigm(b4[h]);
        }
    }
}

// ---------------- big GEMM, tf32 TC, cp.async 3-stage pipeline ----------------
#define GAP 36
#define GBP 36
#define GSTG (128*GAP + 64*GBP)
template<int MODE>
__global__ void __launch_bounds__(256,2) gemm_tc(const float* __restrict__ A,
                                                 const float* __restrict__ WT,
                                                 float* __restrict__ out0,
                                                 float* __restrict__ out1,
                                                 int K)
{
    extern __shared__ uint32_t sh[];
    uint32_t shAddr = (uint32_t)__cvta_generic_to_shared(sh);
    int tid = threadIdx.x, lane = tid & 31, wid = tid >> 5;
    int wm = wid >> 1, wn = wid & 1;       // 4 x 2 warps, 32x32 tiles
    int m0 = blockIdx.y*128, n0 = blockIdx.x*64;
    float acc[2][4][4] = {};
    int ar = tid>>3, ac4 = tid&7;
    int bn = tid>>3, bk4 = tid&7;

    const int NK = K/32;
    auto issue = [&](int kt){
        int k0 = kt*32;
        uint32_t aB = shAddr + (uint32_t)((kt%3)*GSTG*4);
        uint32_t bB = aB + 128*GAP*4;
#pragma unroll
        for (int i=0;i<4;i++){
            int gr = m0 + ar + 32*i;
            uint32_t d = aB + (uint32_t)(((ar+32*i)*GAP + ac4*4)*4);
            if (MODE==1){
                int t = gr & (Lq-1);
                cpa16z(d, &A[(size_t)(gr+Cq-1)*K + k0 + ac4*4], t <= Lq-Cq);
            } else {
                cpa16(d, &A[(size_t)gr*K + k0 + ac4*4]);
            }
        }
#pragma unroll
        for (int i=0;i<2;i++)
            cpa16(bB + (uint32_t)(((bn+32*i)*GBP + bk4*4)*4),
                  &WT[(size_t)(n0 + bn + 32*i)*K + k0 + bk4*4]);
        cpcommit();
    };

    issue(0);
    if (NK>1) issue(1);
#pragma unroll 1
    for (int kt=0; kt<NK; kt++){
        if (kt == NK-1) cpwait<0>(); else cpwait<1>();
        __syncthreads();
        if (kt+2 < NK) issue(kt+2);
        uint32_t aB = shAddr + (uint32_t)((kt%3)*GSTG*4);
        uint32_t bB = aB + 128*GAP*4;
        wtileLL<2,4,4>(ldsmBase(aB, wm*32, GAP, lane), GAP,
                       ldsmBase(bB, wn*32, GBP, lane), GBP, acc);
        __syncthreads();
    }

    int g = lane>>2, tg = lane&3;
#pragma unroll
    for (int mt=0;mt<2;mt++)
#pragma unroll
    for (int nt=0;nt<4;nt++)
#pragma unroll
    for (int e=0;e<4;e++){
        int row = m0 + wm*32 + mt*16 + g + ((e&2)?8:0);
        int col = n0 + wn*32 + nt*8 + 2*tg + (e&1);
        float v = acc[mt][nt][e];
        int b = row >> 12, t = row & (Lq-1);
        if (MODE==0){
            if (col < Hq*DHq){
                int h = col>>7, d = col&127;
                out0[((size_t)(b*Hq+h)*Lq + t)*DHq + d] = f2tf32f(v);   // keys (tf32)
            } else {
                int c2 = col - Hq*DHq; int h = c2>>7, d = c2&127;
                out1[((size_t)(b*Hq+h)*Lq + t)*DHq + d] = v;            // vals fp32
            }
        } else if (MODE==1){
            int h = col>>7, d = col&127;
            out0[((size_t)(b*Hq+h)*Lq + t)*DHq + d] = f2tf32f(v);       // quer (tf32)
        } else {
            if (t <= Lq - Cq)
                out0[((size_t)b*Lq + t + Cq - 1)*DIMq + col] = v;       // final out fp32
        }
    }
}

// ---------------- per-chunk kernels ----------------
#define PT  132
#define PXT 68   // pitch of 128x64 transposed tiles

// ---------------- chunk gradient ----------------
__global__ void __launch_bounds__(256) chunk_grad_kernel()
{
    extern __shared__ uint32_t smu[];
    uint32_t* Ks = smu;            // 64*PT keys (tf32)
    uint32_t* Ab = Ks + 64*PT;     // a=silu(h) (tf32)
    uint32_t* Db = Ab + 64*PT;     // v (fp32), later dpred (tf32) row-major
    uint32_t* XT = Db + 64*PT;     // 128*PXT: dpred^T, later dh^T (tf32)
    uint32_t* Ws = XT + 128*PXT;   // 128*PT weights (w0T, then w1T)
    float* Lr = (float*)(Ws + 128*PT);
    uint32_t KsA = (uint32_t)__cvta_generic_to_shared(Ks);
    uint32_t AbA = (uint32_t)__cvta_generic_to_shared(Ab);
    uint32_t DbA = (uint32_t)__cvta_generic_to_shared(Db);
    uint32_t XTA = (uint32_t)__cvta_generic_to_shared(XT);
    uint32_t WsA = (uint32_t)__cvta_generic_to_shared(Ws);
    int tid = threadIdx.x, lane = tid&31, wid = tid>>5;
    int wm = wid>>2, wn = wid&3;   // 2 x 4 warps
    int g = lane>>2, tg = lane&3;
    int chunk = blockIdx.x;
    int bh = chunk >> 6, t0 = (chunk & 63) << 6;

    const float* kg = d_keys + ((size_t)bh*Lq + t0)*DHq;
    const float* vg = d_vals + ((size_t)bh*Lq + t0)*DHq;
#pragma unroll
    for (int u=tid; u<2048; u+=256){
        int r = u>>5, c = (u&31)*4;
        cpa16(KsA + (r*PT+c)*4, kg + u*4);
        cpa16(DbA + (r*PT+c)*4, vg + u*4);
    }
#pragma unroll
    for (int u=tid; u<4096; u+=256){
        int r = u>>5, c = (u&31)*4;
        cpa16(WsA + (r*PT+c)*4, d_w0T + u*4);
    }
    cpcommit();
    if (tid < 64) Lr[tid] = d_lr[(size_t)bh*Lq + t0 + tid];
    cpwait<0>();
    __syncthreads();

    // m1: h = K @ w0 ; h in regs; a = silu(h) -> Ab
    float hreg[2][4][4] = {};
    wtileLL<2,4,16>(ldsmBase(KsA, wm*32, PT, lane), PT,
                    ldsmBase(WsA, wn*32, PT, lane), PT, hreg);
#pragma unroll
    for (int mt=0;mt<2;mt++)
#pragma unroll
    for (int nt=0;nt<4;nt++)
#pragma unroll
    for (int e=0;e<4;e++){
        int row = wm*32 + mt*16 + g + ((e&2)?8:0);
        int col = wn*32 + nt*8 + 2*tg + (e&1);
        float h = hreg[mt][nt][e];
        Ab[row*PT+col] = f2tf32(h/(1.f+expf(-h)));
    }
    __syncthreads();
#pragma unroll
    for (int u=tid; u<4096; u+=256){
        int r = u>>5, c = (u&31)*4;
        cpa16(WsA + (r*PT+c)*4, d_w1T + u*4);
    }
    cpcommit(); cpwait<0>();
    __syncthreads();

    {   // m2: pred = a @ w1 ; dpred -> Db (row-major) AND XT (transposed)
        float acc[2][4][4] = {};
        wtileLL<2,4,16>(ldsmBase(AbA, wm*32, PT, lane), PT,
                        ldsmBase(WsA, wn*32, PT, lane), PT, acc);
#pragma unroll
        for (int mt=0;mt<2;mt++)
#pragma unroll
        for (int nt=0;nt<4;nt++)
#pragma unroll
        for (int e=0;e<4;e++){
            int row = wm*32 + mt*16 + g + ((e&2)?8:0);
            int col = wn*32 + nt*8 + 2*tg + (e&1);
            float v = __uint_as_float(Db[row*PT+col]);
            uint32_t dp = f2tf32(Lr[row]*(2.f/DHq)*(acc[mt][nt][e] - v));
            Db[row*PT+col]  = dp;
            XT[col*PXT+row] = dp;
        }
    }
    __syncthreads();

    {   // m3: g1^T = dpred^T @ a -> gmem (A from XT via ldsm, B = Ab scalar k-major)
        float acc[4][4][4] = {};
        wtileLS<4,4,8>(ldsmBase(XTA, wm*64, PXT, lane), PXT, Ab, PT, acc, wn*32, lane);
        float* G = d_g1 + (size_t)chunk*DHq*DHq;
#pragma unroll
        for (int mt=0;mt<4;mt++)
#pragma unroll
        for (int nt=0;nt<4;nt++){
            int row = wm*64 + mt*16 + g;
            int col = wn*32 + nt*8 + 2*tg;
            *(float2*)&G[row*DHq + col]     = make_float2(acc[mt][nt][0], acc[mt][nt][1]);
            *(float2*)&G[(row+8)*DHq + col] = make_float2(acc[mt][nt][2], acc[mt][nt][3]);
        }
    }

    {   // m4: da = dpred @ w1^T (B k-major scalar from Ws) ; dh = da*dsilu(h) -> XT (transposed)
        float acc[2][4][4] = {};
        wtileLS<2,4,16>(ldsmBase(DbA, wm*32, PT, lane), PT, Ws, PT, acc, wn*32, lane);
        __syncthreads();    // all m3 XT reads done before overwrite
#pragma unroll
        for (int mt=0;mt<2;mt++)
#pragma unroll
        for (int nt=0;nt<4;nt++)
#pragma unroll
        for (int e=0;e<4;e++){
            int row = wm*32 + mt*16 + g + ((e&2)?8:0);
            int col = wn*32 + nt*8 + 2*tg + (e&1);
            float h = hreg[mt][nt][e];
            float s = 1.f/(1.f+expf(-h));
            XT[col*PXT+row] = f2tf32(acc[mt][nt][e] * s * (1.f + h*(1.f - s)));
        }
    }
    __syncthreads();

    {   // m5: g0^T = dh^T @ K -> gmem (A from XT via ldsm, B = Ks scalar k-major)
        float acc[4][4][4] = {};
        wtileLS<4,4,8>(ldsmBase(XTA, wm*64, PXT, lane), PXT, Ks, PT, acc, wn*32, lane);
        float* G = d_g0 + (size_t)chunk*DHq*DHq;
#pragma unroll
        for (int mt=0;mt<4;mt++)
#pragma unroll
        for (int nt=0;nt<4;nt++){
            int row = wm*64 + mt*16 + g;
            int col = wn*32 + nt*8 + 2*tg;
            *(float2*)&G[row*DHq + col]     = make_float2(acc[mt][nt][0], acc[mt][nt][1]);
            *(float2*)&G[(row+8)*DHq + col] = make_float2(acc[mt][nt][2], acc[mt][nt][3]);
        }
    }
}

// ---------------- scan (transposed layout; writes tf32-rounded) ----------------
__global__ void __launch_bounds__(256) scan_kernel()
{
    __shared__ float ams[Nq], dcs[Nq];
    int gid = blockIdx.x*256 + threadIdx.x;
    int bh = gid >> 14;
    int e  = gid & 16383;
    if (threadIdx.x < Nq){
        ams[threadIdx.x] = d_am[(size_t)bh*Nq + threadIdx.x];
        dcs[threadIdx.x] = d_dc[(size_t)bh*Nq + threadIdx.x];
    }
    __syncthreads();
    float m0=0.f,u0=0.f,m1=0.f,u1=0.f;
    float wa = d_w0T[e], wb = d_w1T[e];
    size_t base = ((size_t)bh*Nq)*16384 + e;
    for (int n=0;n<Nq;n++){
        float a = ams[n], d = 1.f - dcs[n];
        size_t off = base + (size_t)n*16384;
        m0 = a*m0 - d_g0[off];  u0 = d*u0 + m0;  d_w0t[off] = f2tf32f(wa + u0);
        m1 = a*m1 - d_g1[off];  u1 = d*u1 + m1;  d_w1t[off] = f2tf32f(wb + u1);
    }
}

// ---------------- retrieve MLP + RMSNorm + gate (in-place tile, 2 CTA/SM) ----------------
__global__ void __launch_bounds__(256,2) retrieve_kernel(const float* __restrict__ gamma)
{
    extern __shared__ uint32_t smr[];
    uint32_t* QA = smr;            // 64*PT: q -> a -> o (in place)
    uint32_t* Ws = QA + 64*PT;     // 128*PT: w0t, then w1t
    uint32_t QAA = (uint32_t)__cvta_generic_to_shared(QA);
    uint32_t WsA = (uint32_t)__cvta_generic_to_shared(Ws);
    int tid = threadIdx.x, lane = tid&31, wid = tid>>5;
    int wm = wid>>2, wn = wid&3;
    int g = lane>>2, tg = lane&3;
    int chunk = blockIdx.x;
    int bh = chunk >> 6, n = chunk & 63;
    int b = bh >> 2, h = bh & 3;

    const float* qg  = d_quer + ((size_t)bh*Lq + n*Cq)*DHq;
    const float* w0c = d_w0t + (size_t)chunk*DHq*DHq;
    const float* w1c = d_w1t + (size_t)chunk*DHq*DHq;
#pragma unroll
    for (int u=tid; u<2048; u+=256){
        int r = u>>5, c = (u&31)*4;
        cpa16(QAA + (r*PT+c)*4, qg + u*4);
    }
#pragma unroll
    for (int u=tid; u<4096; u+=256){
        int r = u>>5, c = (u&31)*4;
        cpa16(WsA + (r*PT+c)*4, w0c + u*4);
    }
    cpcommit(); cpwait<0>();
    __syncthreads();

    // m1: a = silu(q @ w0_t)  — compute to regs, sync, write in place
    float acc1[2][4][4] = {};
    wtileLL<2,4,16>(ldsmBase(QAA, wm*32, PT, lane), PT,
                    ldsmBase(WsA, wn*32, PT, lane), PT, acc1);
    __syncthreads();           // everyone done reading q and w0t
#pragma unroll
    for (int u=tid; u<4096; u+=256){     // start w1t load into freed Ws
        int r = u>>5, c = (u&31)*4;
        cpa16(WsA + (r*PT+c)*4, w1c + u*4);
    }
    cpcommit();
#pragma unroll
    for (int mt=0;mt<2;mt++)
#pragma unroll
    for (int nt=0;nt<4;nt++)
#pragma unroll
    for (int e=0;e<4;e++){
        int row = wm*32 + mt*16 + g + ((e&2)?8:0);
        int col = wn*32 + nt*8 + 2*tg + (e&1);
        float hh = acc1[mt][nt][e];
        QA[row*PT+col] = f2tf32(hh/(1.f+expf(-hh)));
    }
    cpwait<0>();
    __syncthreads();

    // m2: o = a @ w1_t — compute to regs, sync, write in place (fp32 bits)
    float acc2[2][4][4] = {};
    wtileLL<2,4,16>(ldsmBase(QAA, wm*32, PT, lane), PT,
                    ldsmBase(WsA, wn*32, PT, lane), PT, acc2);
    __syncthreads();
#pragma unroll
    for (int mt=0;mt<2;mt++)
#pragma unroll
    for (int nt=0;nt<4;nt++)
#pragma unroll
    for (int e=0;e<4;e++){
        int row = wm*32 + mt*16 + g + ((e&2)?8:0);
        int col = wn*32 + nt*8 + 2*tg + (e&1);
        QA[row*PT+col] = __float_as_uint(acc2[mt][nt][e]);
    }
    __syncthreads();

    const float* Of = (const float*)QA;
    int w = tid >> 5;
#pragma unroll
    for (int rr=0; rr<8; rr++){
        int row = w*8 + rr;
        float v0 = Of[row*PT + lane];
        float v1 = Of[row*PT + lane + 32];
        float v2 = Of[row*PT + lane + 64];
        float v3 = Of[row*PT + lane + 96];
        float ss = v0*v0 + v1*v1 + v2*v2 + v3*v3;
#pragma unroll
        for (int off=16;off;off>>=1) ss += __shfl_xor_sync(0xffffffffu, ss, off);
        float sc = rsqrtf(ss*(1.f/DHq) + EPSq);
        int t = n*Cq + row;
        float gt = d_gatev[((size_t)b*Lq + t)*Hq + h];
        float* dst = d_comb + ((size_t)b*Lq + t)*DIMq + h*DHq;
        dst[lane     ] = f2tf32f(v0*sc*(gamma[h*DHq + lane     ] + 1.f)*gt);
        dst[lane + 32] = f2tf32f(v1*sc*(gamma[h*DHq + lane + 32] + 1.f)*gt);
        dst[lane + 64] = f2tf32f(v2*sc*(gamma[h*DHq + lane + 64] + 1.f)*gt);
        dst[lane + 96] = f2tf32f(v3*sc*(gamma[h*DHq + lane + 96] + 1.f)*gt);
    }
}

// ---------------- empty-embed fill ----------------
__global__ void empty_fill_kernel(const float* __restrict__ emb, float* __restrict__ out)
{
    int gid = blockIdx.x*blockDim.x + threadIdx.x;
    int total = Bq*(Cq-1)*DIMq;
    if (gid >= total) return;
    int d = gid & (DIMq-1);
    int row = gid / DIMq;
    int b = row / (Cq-1), t = row % (Cq-1);
    out[((size_t)b*Lq + t)*DIMq + d] = emb[d];
}

// ---------------- launch ----------------
extern "C" void kernel_launch(void* const* d_in, const int* in_sizes, int n_in,
                              void* d_out, int out_size)
{
    const float* seq      = (const float*)d_in[0];
    const float* ss       = (const float*)d_in[1];
    const float* rs       = (const float*)d_in[2];
    const float* w_q      = (const float*)d_in[3];
    const float* w_kv     = (const float*)d_in[4];
    const float* w_ada    = (const float*)d_in[5];
    const float* w_mom    = (const float*)d_in[6];
    const float* w_dec    = (const float*)d_in[7];
    const float* w0       = (const float*)d_in[8];
    const float* w1       = (const float*)d_in[9];
    const float* gamma    = (const float*)d_in[10];
    const float* w_gate   = (const float*)d_in[11];
    const float* w_comb   = (const float*)d_in[12];
    const float* emb      = (const float*)d_in[13];
    float* out = (float*)d_out;

    float *p_snorm, *p_rnorm, *p_keys, *p_vals, *p_quer, *p_comb;
    float *p_wkvT, *p_wqT, *p_wcT, *p_w0T, *p_w1T;
    cudaGetSymbolAddress((void**)&p_snorm, d_s_norm);
    cudaGetSymbolAddress((void**)&p_rnorm, d_r_norm);
    cudaGetSymbolAddress((void**)&p_keys,  d_keys);
    cudaGetSymbolAddress((void**)&p_vals,  d_vals);
    cudaGetSymbolAddress((void**)&p_quer,  d_quer);
    cudaGetSymbolAddress((void**)&p_comb,  d_comb);
    cudaGetSymbolAddress((void**)&p_wkvT,  d_wkvT);
    cudaGetSymbolAddress((void**)&p_wqT,   d_wqT);
    cudaGetSymbolAddress((void**)&p_wcT,   d_wcT);
    cudaGetSymbolAddress((void**)&p_w0T,   d_w0T);
    cudaGetSymbolAddress((void**)&p_w1T,   d_w1T);

    const int SMEM_GEMM = 3*GSTG*4;                               // 82944 B
    const int SMEM_G = (3*64*PT + 128*PXT + 128*PT)*4 + 256;      // ~204 KB
    const int SMEM_R = (64*PT + 128*PT)*4;                        // 101376 B
    cudaFuncSetAttribute(gemm_tc<0>, cudaFuncAttributeMaxDynamicSharedMemorySize, SMEM_GEMM);
    cudaFuncSetAttribute(gemm_tc<1>, cudaFuncAttributeMaxDynamicSharedMemorySize, SMEM_GEMM);
    cudaFuncSetAttribute(gemm_tc<2>, cudaFuncAttributeMaxDynamicSharedMemorySize, SMEM_GEMM);
    cudaFuncSetAttribute(chunk_grad_kernel, cudaFuncAttributeMaxDynamicSharedMemorySize, SMEM_G);
    cudaFuncSetAttribute(retrieve_kernel,   cudaFuncAttributeMaxDynamicSharedMemorySize, SMEM_R);

    // fork/join streams (capture-safe)
    cudaStream_t s1, s2;
    cudaStreamCreateWithFlags(&s1, cudaStreamNonBlocking);
    cudaStreamCreateWithFlags(&s2, cudaStreamNonBlocking);
    cudaEvent_t e0, et, en, eq, em;
    cudaEventCreateWithFlags(&e0, cudaEventDisableTiming);
    cudaEventCreateWithFlags(&et, cudaEventDisableTiming);
    cudaEventCreateWithFlags(&en, cudaEventDisableTiming);
    cudaEventCreateWithFlags(&eq, cudaEventDisableTiming);
    cudaEventCreateWithFlags(&em, cudaEventDisableTiming);

    cudaEventRecord(e0, 0);
    cudaStreamWaitEvent(s1, e0, 0);
    cudaStreamWaitEvent(s2, e0, 0);

    // s1: weight transposes + empty fill
    transpose_kernel<<<dim3(1024/32, 512/32), dim3(32,8), 0, s1>>>(w_kv,   p_wkvT, DIMq, 2*Hq*DHq);
    transpose_kernel<<<dim3(512/32,  512/32), dim3(32,8), 0, s1>>>(w_q,    p_wqT,  DIMq, Hq*DHq);
    transpose_kernel<<<dim3(512/32,  512/32), dim3(32,8), 0, s1>>>(w_comb, p_wcT,  Hq*DHq, DIMq);
    transpose_kernel<<<dim3(4,4),             dim3(32,8), 0, s1>>>(w0,     p_w0T,  DHq, DHq);
    transpose_kernel<<<dim3(4,4),             dim3(32,8), 0, s1>>>(w1,     p_w1T,  DHq, DHq);
    empty_fill_kernel<<<(Bq*(Cq-1)*DIMq + 255)/256, 256, 0, s1>>>(emb, out);
    cudaEventRecord(et, s1);

    // main: rmsnorms + fused projections
    norm_kernel<<<Bq*Lq, 128>>>(seq, ss, rs, w_ada, w_gate);
    cudaEventRecord(en, 0);

    // s1: chunk means -> momdec
    cudaStreamWaitEvent(s1, en, 0);
    chunk_mean_kernel<<<Bq*Nq, 512, 0, s1>>>();
    momdec_kernel<<<(Bq*Nq*32 + 255)/256, 256, 0, s1>>>(w_mom, w_dec);
    cudaEventRecord(em, s1);

    // s2: query projection
    cudaStreamWaitEvent(s2, en, 0);
    cudaStreamWaitEvent(s2, et, 0);
    gemm_tc<1><<<dim3((Hq*DHq)/64, (Bq*Lq)/128), 256, SMEM_GEMM, s2>>>(p_rnorm, p_wqT, p_quer, nullptr, DIMq);
    cudaEventRecord(eq, s2);

    // main chain
    cudaStreamWaitEvent(0, et, 0);
    gemm_tc<0><<<dim3((2*Hq*DHq)/64, (Bq*Lq)/128), 256, SMEM_GEMM>>>(p_snorm, p_wkvT, p_keys, p_vals, DIMq);
    chunk_grad_kernel<<<NCHUNK, 256, SMEM_G>>>();
    cudaStreamWaitEvent(0, em, 0);
    scan_kernel<<<(BHq*16384)/256, 256>>>();
    cudaStreamWaitEvent(0, eq, 0);
    retrieve_kernel<<<NCHUNK, 256, SMEM_R>>>(gamma);
    gemm_tc<2><<<dim3(DIMq/64, (Bq*Lq)/128), 256, SMEM_GEMM>>>(p_comb, p_wcT, out, nullptr, Hq*DHq);

    cudaStreamCaptureStatus cap = cudaStreamCaptureStatusNone;
    cudaStreamIsCapturing(0, &cap);
    if (cap == cudaStreamCaptureStatusNone){
        cudaStreamDestroy(s1); cudaStreamDestroy(s2);
        cudaEventDestroy(e0); cudaEventDestroy(et); cudaEventDestroy(en);
        cudaEventDestroy(eq); cudaEventDestroy(em);
    }
}